// round 2
// baseline (speedup 1.0000x reference)
#include <cuda_runtime.h>
#include <cuda_bf16.h>
#include <cstdint>

// ---------------------------------------------------------------------------
// SAGE 2-layer: h1 = BN(relu(agg1@W1l + b1 + x@W1r)); out = relu(BN(relu(...)))
// Scratch in __device__ globals (no allocations allowed).
// edge_index is int32 (JAX x64 disabled -> int64 request materializes int32).
// ---------------------------------------------------------------------------

#define MAXN 200704
__device__ float g_agg[(size_t)MAXN * 128];
__device__ float g_h1[(size_t)MAXN * 128];
__device__ float g_stats[8192];   // [2][128][32] : sum slots then sumsq slots
__device__ float g_scale[128];
__device__ float g_shift[128];

// Vector reduction (no return) — sm_90+ PTX
__device__ __forceinline__ void red_add4(float* p, float4 v) {
    asm volatile("red.global.add.v4.f32 [%0], {%1,%2,%3,%4};"
                 :: "l"(p), "f"(v.x), "f"(v.y), "f"(v.z), "f"(v.w)
                 : "memory");
}

// ---------------------------------------------------------------------------
// Scatter: agg[dst] += feat[src] (optionally with BN affine applied to feat)
// One thread per (edge, 4-feature chunk). Consecutive threads share an edge ->
// coalesced float4 gathers.
// ---------------------------------------------------------------------------
template <int F, bool BN>
__global__ void sage_scatter(const float* __restrict__ feat,
                             const int* __restrict__ ei,
                             int E, float* __restrict__ aggout) {
    const int PER = F / 4;
    int t = blockIdx.x * blockDim.x + threadIdx.x;
    if (t >= E * PER) return;
    int e  = t / PER;
    int f4 = (t - e * PER) * 4;
    int s = ei[e];
    int d = ei[E + e];
    float4 v = *(const float4*)(feat + (size_t)s * F + f4);
    if (BN) {
        float4 sc = *(const float4*)(g_scale + f4);
        float4 sh = *(const float4*)(g_shift + f4);
        v.x = fmaf(v.x, sc.x, sh.x);
        v.y = fmaf(v.y, sc.y, sh.y);
        v.z = fmaf(v.z, sc.z, sh.z);
        v.w = fmaf(v.w, sc.w, sh.w);
    }
    red_add4(aggout + (size_t)d * F + f4, v);
}

// ---------------------------------------------------------------------------
// Fused dual GEMM + bias + relu + BN-stat partials.
// out[r, :] = relu(agg[r,:]@Wl + xin'[r,:]@Wr + bias), xin' = BN(xin) if BNX.
// Tile: 64 rows x 128 cols per 256-thread block; 4 rows x 8 cols per thread.
// Stats (sum, sum^2 per column over rows) block-reduced then atomically added
// into 32 slots per column (contention amortized).
// ---------------------------------------------------------------------------
template <int K, bool BNX>
__global__ void __launch_bounds__(256, 1)
sage_gemm(const float* __restrict__ agg,
          const float* __restrict__ xin,
          const float* __restrict__ Wl,
          const float* __restrict__ Wr,
          const float* __restrict__ bias,
          float* __restrict__ out, int n) {
    extern __shared__ float smem[];
    float* sWl = smem;                 // K*128
    float* sWr = smem + K * 128;       // K*128
    float* sA  = smem + 2 * K * 128;   // 64*K
    float* sX  = sA + 64 * K;          // 64*K

    const int tid  = threadIdx.x;
    const int row0 = blockIdx.x * 64;

    // Stage weights
    for (int i = tid * 4; i < K * 128; i += 1024) {
        *(float4*)(sWl + i) = *(const float4*)(Wl + i);
        *(float4*)(sWr + i) = *(const float4*)(Wr + i);
    }
    // Stage input tiles (apply BN affine to the root-term input if requested)
    for (int i = tid * 4; i < 64 * K; i += 1024) {
        int r = i / K, c = i - r * K;
        int gr = row0 + r;
        float4 av = make_float4(0.f, 0.f, 0.f, 0.f);
        float4 xv = av;
        if (gr < n) {
            av = *(const float4*)(agg + (size_t)gr * K + c);
            xv = *(const float4*)(xin + (size_t)gr * K + c);
            if (BNX) {
                float4 sc = *(const float4*)(g_scale + c);
                float4 sh = *(const float4*)(g_shift + c);
                xv.x = fmaf(xv.x, sc.x, sh.x);
                xv.y = fmaf(xv.y, sc.y, sh.y);
                xv.z = fmaf(xv.z, sc.z, sh.z);
                xv.w = fmaf(xv.w, sc.w, sh.w);
            }
        }
        *(float4*)(sA + i) = av;
        *(float4*)(sX + i) = xv;
    }
    __syncthreads();

    const int col0 = (tid & 15) * 8;
    const int r0   = (tid >> 4) * 4;

    float acc[4][8];
#pragma unroll
    for (int r = 0; r < 4; r++)
#pragma unroll
        for (int c = 0; c < 8; c++) acc[r][c] = 0.f;

    for (int k = 0; k < K; k++) {
        float4 wl0 = *(float4*)(sWl + k * 128 + col0);
        float4 wl1 = *(float4*)(sWl + k * 128 + col0 + 4);
        float4 wr0 = *(float4*)(sWr + k * 128 + col0);
        float4 wr1 = *(float4*)(sWr + k * 128 + col0 + 4);
#pragma unroll
        for (int r = 0; r < 4; r++) {
            const float a = sA[(r0 + r) * K + k];
            const float b = sX[(r0 + r) * K + k];
            acc[r][0] = fmaf(a, wl0.x, acc[r][0]); acc[r][0] = fmaf(b, wr0.x, acc[r][0]);
            acc[r][1] = fmaf(a, wl0.y, acc[r][1]); acc[r][1] = fmaf(b, wr0.y, acc[r][1]);
            acc[r][2] = fmaf(a, wl0.z, acc[r][2]); acc[r][2] = fmaf(b, wr0.z, acc[r][2]);
            acc[r][3] = fmaf(a, wl0.w, acc[r][3]); acc[r][3] = fmaf(b, wr0.w, acc[r][3]);
            acc[r][4] = fmaf(a, wl1.x, acc[r][4]); acc[r][4] = fmaf(b, wr1.x, acc[r][4]);
            acc[r][5] = fmaf(a, wl1.y, acc[r][5]); acc[r][5] = fmaf(b, wr1.y, acc[r][5]);
            acc[r][6] = fmaf(a, wl1.z, acc[r][6]); acc[r][6] = fmaf(b, wr1.z, acc[r][6]);
            acc[r][7] = fmaf(a, wl1.w, acc[r][7]); acc[r][7] = fmaf(b, wr1.w, acc[r][7]);
        }
    }

    float bs[8];
#pragma unroll
    for (int c = 0; c < 8; c++) bs[c] = bias[col0 + c];

    __syncthreads();                 // about to reuse sA as reduction buffer
    float* redS = sA;                // 16*128
    float* redQ = sA + 2048;         // 16*128

    float psum[8], psq[8];
#pragma unroll
    for (int c = 0; c < 8; c++) { psum[c] = 0.f; psq[c] = 0.f; }

#pragma unroll
    for (int r = 0; r < 4; r++) {
        int gr = row0 + r0 + r;
        if (gr >= n) continue;
        float v[8];
#pragma unroll
        for (int c = 0; c < 8; c++) {
            float tval = fmaxf(acc[r][c] + bs[c], 0.f);
            v[c] = tval;
            psum[c] += tval;
            psq[c]  += tval * tval;
        }
        float4* op = (float4*)(out + (size_t)gr * 128 + col0);
        op[0] = make_float4(v[0], v[1], v[2], v[3]);
        op[1] = make_float4(v[4], v[5], v[6], v[7]);
    }

    const int rowgrp = tid >> 4;
#pragma unroll
    for (int c = 0; c < 8; c++) {
        redS[rowgrp * 128 + col0 + c] = psum[c];
        redQ[rowgrp * 128 + col0 + c] = psq[c];
    }
    __syncthreads();
    if (tid < 128) {
        float s = 0.f, q = 0.f;
#pragma unroll
        for (int g = 0; g < 16; g++) {
            s += redS[g * 128 + tid];
            q += redQ[g * 128 + tid];
        }
        int slot = blockIdx.x & 31;
        atomicAdd(&g_stats[tid * 32 + slot], s);
        atomicAdd(&g_stats[4096 + tid * 32 + slot], q);
    }
}

// ---------------------------------------------------------------------------
// Finalize BN: mu/var (biased) -> scale/shift
// ---------------------------------------------------------------------------
__global__ void bn_finalize(const float* __restrict__ gamma,
                            const float* __restrict__ beta, float inv_n) {
    int c = threadIdx.x;  // 128 threads
    float s = 0.f, q = 0.f;
#pragma unroll
    for (int j = 0; j < 32; j++) {
        s += g_stats[c * 32 + j];
        q += g_stats[4096 + c * 32 + j];
    }
    float mu  = s * inv_n;
    float var = q * inv_n - mu * mu;
    float sc  = gamma[c] * rsqrtf(var + 1e-5f);
    g_scale[c] = sc;
    g_shift[c] = beta[c] - mu * sc;
}

// Final: out = relu(out * scale + shift), in place
__global__ void bn_apply_relu(float* __restrict__ out, int total4) {
    int i = blockIdx.x * blockDim.x + threadIdx.x;
    if (i >= total4) return;
    float4 v = ((float4*)out)[i];
    int c = (i & 31) * 4;
    float4 sc = *(const float4*)(g_scale + c);
    float4 sh = *(const float4*)(g_shift + c);
    v.x = fmaxf(fmaf(v.x, sc.x, sh.x), 0.f);
    v.y = fmaxf(fmaf(v.y, sc.y, sh.y), 0.f);
    v.z = fmaxf(fmaf(v.z, sc.z, sh.z), 0.f);
    v.w = fmaxf(fmaf(v.w, sc.w, sh.w), 0.f);
    ((float4*)out)[i] = v;
}

// ---------------------------------------------------------------------------
extern "C" void kernel_launch(void* const* d_in, const int* in_sizes, int n_in,
                              void* d_out, int out_size) {
    const float* x   = (const float*)d_in[0];
    const int*   ei  = (const int*)d_in[1];
    const float* W1l = (const float*)d_in[2];
    const float* b1  = (const float*)d_in[3];
    const float* W1r = (const float*)d_in[4];
    const float* g1  = (const float*)d_in[5];
    const float* be1 = (const float*)d_in[6];
    const float* W2l = (const float*)d_in[7];
    const float* b2  = (const float*)d_in[8];
    const float* W2r = (const float*)d_in[9];
    const float* g2  = (const float*)d_in[10];
    const float* be2 = (const float*)d_in[11];
    float* out = (float*)d_out;

    const int n = in_sizes[0] / 64;
    const int E = in_sizes[1] / 2;

    void *aggp, *h1p, *statp;
    cudaGetSymbolAddress(&aggp, g_agg);
    cudaGetSymbolAddress(&h1p, g_h1);
    cudaGetSymbolAddress(&statp, g_stats);
    float* agg = (float*)aggp;
    float* h1  = (float*)h1p;

    const int SMEM1 = (2 * 64 * 128 + 2 * 64 * 64) * 4;    // 96 KB
    const int SMEM2 = (2 * 128 * 128 + 2 * 64 * 128) * 4;  // 192 KB
    cudaFuncSetAttribute(sage_gemm<64, false>,
                         cudaFuncAttributeMaxDynamicSharedMemorySize, SMEM1);
    cudaFuncSetAttribute(sage_gemm<128, true>,
                         cudaFuncAttributeMaxDynamicSharedMemorySize, SMEM2);

    const int gemm_blocks = (n + 63) / 64;

    // ---------------- Layer 1 ----------------
    cudaMemsetAsync(aggp, 0, (size_t)n * 64 * sizeof(float));
    cudaMemsetAsync(statp, 0, 8192 * sizeof(float));
    {
        int total = E * 16;  // E * (64/4)
        sage_scatter<64, false><<<(total + 255) / 256, 256>>>(x, ei, E, agg);
    }
    sage_gemm<64, false><<<gemm_blocks, 256, SMEM1>>>(agg, x, W1l, W1r, b1, h1, n);
    bn_finalize<<<1, 128>>>(g1, be1, 1.0f / (float)n);

    // ---------------- Layer 2 ----------------
    cudaMemsetAsync(aggp, 0, (size_t)n * 128 * sizeof(float));
    cudaMemsetAsync(statp, 0, 8192 * sizeof(float));
    {
        int total = E * 32;  // E * (128/4)
        sage_scatter<128, true><<<(total + 255) / 256, 256>>>(h1, ei, E, agg);
    }
    sage_gemm<128, true><<<gemm_blocks, 256, SMEM2>>>(agg, h1, W2l, W2r, b2, out, n);
    bn_finalize<<<1, 128>>>(g2, be2, 1.0f / (float)n);
    bn_apply_relu<<<((n * 32) + 255) / 256, 256>>>(out, n * 32);
}

// round 3
// speedup vs baseline: 1.1298x; 1.1298x over previous
#include <cuda_runtime.h>
#include <cuda_bf16.h>
#include <cstdint>

// ---------------------------------------------------------------------------
// SAGE 2-layer GNN. edge_index is int32. Scratch in __device__ globals.
// GEMMs use Blackwell packed fma.rn.f32x2 (2 FMA/op). Scatter for layer 2 is
// split into two feature-half passes so h1-half + agg-half (~102MB) stay
// resident in the 126MB L2.
// ---------------------------------------------------------------------------

typedef unsigned long long u64;

#define MAXN 200704
__device__ float g_agg[(size_t)MAXN * 128];
__device__ float g_h1[(size_t)MAXN * 128];
__device__ float g_stats[8192];   // [2][128][32]
__device__ float g_scale[128];
__device__ float g_shift[128];

__device__ __forceinline__ void red_add4(float* p, float4 v) {
    asm volatile("red.global.add.v4.f32 [%0], {%1,%2,%3,%4};"
                 :: "l"(p), "f"(v.x), "f"(v.y), "f"(v.z), "f"(v.w)
                 : "memory");
}

__device__ __forceinline__ void ffma2(u64& d, u64 a, u64 b) {
    asm("fma.rn.f32x2 %0, %1, %2, %0;" : "+l"(d) : "l"(a), "l"(b));
}
__device__ __forceinline__ u64 pack2(float x) {
    u64 r;
    asm("mov.b64 %0, {%1, %1};" : "=l"(r) : "f"(x));
    return r;
}
__device__ __forceinline__ float2 unpack2(u64 v) {
    float2 f;
    asm("mov.b64 {%0, %1}, %2;" : "=f"(f.x), "=f"(f.y) : "l"(v));
    return f;
}

// ---------------------------------------------------------------------------
// Scatter a span of SPANQ*4 features starting at f_lo:
//   agg[dst, f_lo:f_lo+span] += bn?(feat[src, f_lo:f_lo+span])
// ---------------------------------------------------------------------------
template <int F, int SPANQ, bool BN>
__global__ void sage_scatter(const float* __restrict__ feat,
                             const int* __restrict__ ei,
                             int E, float* __restrict__ aggout, int f_lo) {
    int t = blockIdx.x * blockDim.x + threadIdx.x;
    if (t >= E * SPANQ) return;
    int e  = t / SPANQ;
    int f4 = f_lo + (t - e * SPANQ) * 4;
    int s = ei[e];
    int d = ei[E + e];
    float4 v = *(const float4*)(feat + (size_t)s * F + f4);
    if (BN) {
        float4 sc = *(const float4*)(g_scale + f4);
        float4 sh = *(const float4*)(g_shift + f4);
        v.x = fmaf(v.x, sc.x, sh.x);
        v.y = fmaf(v.y, sc.y, sh.y);
        v.z = fmaf(v.z, sc.z, sh.z);
        v.w = fmaf(v.w, sc.w, sh.w);
    }
    red_add4(aggout + (size_t)d * F + f4, v);
}

// ---------------------------------------------------------------------------
// Fused dual GEMM + bias + relu + BN-stat partials (f32x2 packed FMA).
// 64 rows x 128 cols per 256-thread block; 4 rows x 8 cols (4 pairs) / thread.
// ---------------------------------------------------------------------------
template <int K, bool BNX>
__global__ void __launch_bounds__(256, 2)
sage_gemm(const float* __restrict__ agg,
          const float* __restrict__ xin,
          const float* __restrict__ Wl,
          const float* __restrict__ Wr,
          const float* __restrict__ bias,
          float* __restrict__ out, int n) {
    extern __shared__ float smem[];
    float* sWl = smem;                 // K*128
    float* sWr = smem + K * 128;       // K*128
    float* sA  = smem + 2 * K * 128;   // 64*K
    float* sX  = sA + 64 * K;          // 64*K

    const int tid  = threadIdx.x;
    const int row0 = blockIdx.x * 64;

    for (int i = tid * 4; i < K * 128; i += 1024) {
        *(float4*)(sWl + i) = *(const float4*)(Wl + i);
        *(float4*)(sWr + i) = *(const float4*)(Wr + i);
    }
    for (int i = tid * 4; i < 64 * K; i += 1024) {
        int r = i / K, c = i - r * K;
        int gr = row0 + r;
        float4 av = make_float4(0.f, 0.f, 0.f, 0.f);
        float4 xv = av;
        if (gr < n) {
            av = *(const float4*)(agg + (size_t)gr * K + c);
            xv = *(const float4*)(xin + (size_t)gr * K + c);
            if (BNX) {
                float4 sc = *(const float4*)(g_scale + c);
                float4 sh = *(const float4*)(g_shift + c);
                xv.x = fmaf(xv.x, sc.x, sh.x);
                xv.y = fmaf(xv.y, sc.y, sh.y);
                xv.z = fmaf(xv.z, sc.z, sh.z);
                xv.w = fmaf(xv.w, sc.w, sh.w);
            }
        }
        *(float4*)(sA + i) = av;
        *(float4*)(sX + i) = xv;
    }
    __syncthreads();

    const int col0 = (tid & 15) * 8;
    const int r0   = (tid >> 4) * 4;

    u64 acc[4][4];
#pragma unroll
    for (int r = 0; r < 4; r++)
#pragma unroll
        for (int p = 0; p < 4; p++) acc[r][p] = 0ull;

#pragma unroll 2
    for (int k = 0; k < K; k++) {
        const ulonglong2 wl0 = *(const ulonglong2*)(sWl + k * 128 + col0);
        const ulonglong2 wl1 = *(const ulonglong2*)(sWl + k * 128 + col0 + 4);
        const ulonglong2 wr0 = *(const ulonglong2*)(sWr + k * 128 + col0);
        const ulonglong2 wr1 = *(const ulonglong2*)(sWr + k * 128 + col0 + 4);
#pragma unroll
        for (int r = 0; r < 4; r++) {
            const u64 a2 = pack2(sA[(r0 + r) * K + k]);
            const u64 b2 = pack2(sX[(r0 + r) * K + k]);
            ffma2(acc[r][0], a2, wl0.x); ffma2(acc[r][0], b2, wr0.x);
            ffma2(acc[r][1], a2, wl0.y); ffma2(acc[r][1], b2, wr0.y);
            ffma2(acc[r][2], a2, wl1.x); ffma2(acc[r][2], b2, wr1.x);
            ffma2(acc[r][3], a2, wl1.y); ffma2(acc[r][3], b2, wr1.y);
        }
    }

    float bs[8];
#pragma unroll
    for (int c = 0; c < 8; c++) bs[c] = bias[col0 + c];

    __syncthreads();                 // reuse sA as reduction buffer
    float* redS = sA;                // 16*128
    float* redQ = sA + 2048;         // 16*128

    float psum[8], psq[8];
#pragma unroll
    for (int c = 0; c < 8; c++) { psum[c] = 0.f; psq[c] = 0.f; }

#pragma unroll
    for (int r = 0; r < 4; r++) {
        int gr = row0 + r0 + r;
        if (gr >= n) continue;
        float v[8];
#pragma unroll
        for (int p = 0; p < 4; p++) {
            float2 f = unpack2(acc[r][p]);
            v[p * 2]     = f.x;
            v[p * 2 + 1] = f.y;
        }
        // pairs map to columns: p0->(c0,c1) p1->(c2,c3) p2->(c4,c5) p3->(c6,c7)
#pragma unroll
        for (int c = 0; c < 8; c++) {
            float tval = fmaxf(v[c] + bs[c], 0.f);
            v[c] = tval;
            psum[c] += tval;
            psq[c]  += tval * tval;
        }
        float4* op = (float4*)(out + (size_t)gr * 128 + col0);
        op[0] = make_float4(v[0], v[1], v[2], v[3]);
        op[1] = make_float4(v[4], v[5], v[6], v[7]);
    }

    const int rowgrp = tid >> 4;
#pragma unroll
    for (int c = 0; c < 8; c++) {
        redS[rowgrp * 128 + col0 + c] = psum[c];
        redQ[rowgrp * 128 + col0 + c] = psq[c];
    }
    __syncthreads();
    if (tid < 128) {
        float s = 0.f, q = 0.f;
#pragma unroll
        for (int g = 0; g < 16; g++) {
            s += redS[g * 128 + tid];
            q += redQ[g * 128 + tid];
        }
        int slot = blockIdx.x & 31;
        atomicAdd(&g_stats[tid * 32 + slot], s);
        atomicAdd(&g_stats[4096 + tid * 32 + slot], q);
    }
}

__global__ void bn_finalize(const float* __restrict__ gamma,
                            const float* __restrict__ beta, float inv_n) {
    int c = threadIdx.x;  // 128 threads
    float s = 0.f, q = 0.f;
#pragma unroll
    for (int j = 0; j < 32; j++) {
        s += g_stats[c * 32 + j];
        q += g_stats[4096 + c * 32 + j];
    }
    float mu  = s * inv_n;
    float var = q * inv_n - mu * mu;
    float sc  = gamma[c] * rsqrtf(var + 1e-5f);
    g_scale[c] = sc;
    g_shift[c] = beta[c] - mu * sc;
}

__global__ void bn_apply_relu(float* __restrict__ out, int total4) {
    int i = blockIdx.x * blockDim.x + threadIdx.x;
    if (i >= total4) return;
    float4 v = ((float4*)out)[i];
    int c = (i & 31) * 4;
    float4 sc = *(const float4*)(g_scale + c);
    float4 sh = *(const float4*)(g_shift + c);
    v.x = fmaxf(fmaf(v.x, sc.x, sh.x), 0.f);
    v.y = fmaxf(fmaf(v.y, sc.y, sh.y), 0.f);
    v.z = fmaxf(fmaf(v.z, sc.z, sh.z), 0.f);
    v.w = fmaxf(fmaf(v.w, sc.w, sh.w), 0.f);
    ((float4*)out)[i] = v;
}

// ---------------------------------------------------------------------------
extern "C" void kernel_launch(void* const* d_in, const int* in_sizes, int n_in,
                              void* d_out, int out_size) {
    const float* x   = (const float*)d_in[0];
    const int*   ei  = (const int*)d_in[1];
    const float* W1l = (const float*)d_in[2];
    const float* b1  = (const float*)d_in[3];
    const float* W1r = (const float*)d_in[4];
    const float* g1  = (const float*)d_in[5];
    const float* be1 = (const float*)d_in[6];
    const float* W2l = (const float*)d_in[7];
    const float* b2  = (const float*)d_in[8];
    const float* W2r = (const float*)d_in[9];
    const float* g2  = (const float*)d_in[10];
    const float* be2 = (const float*)d_in[11];
    float* out = (float*)d_out;

    const int n = in_sizes[0] / 64;
    const int E = in_sizes[1] / 2;

    void *aggp, *h1p, *statp;
    cudaGetSymbolAddress(&aggp, g_agg);
    cudaGetSymbolAddress(&h1p, g_h1);
    cudaGetSymbolAddress(&statp, g_stats);
    float* agg = (float*)aggp;
    float* h1  = (float*)h1p;

    const int SMEM1 = (2 * 64 * 128 + 2 * 64 * 64) * 4;    // 96 KB
    const int SMEM2 = (2 * 128 * 128 + 2 * 64 * 128) * 4;  // 192 KB
    cudaFuncSetAttribute(sage_gemm<64, false>,
                         cudaFuncAttributeMaxDynamicSharedMemorySize, SMEM1);
    cudaFuncSetAttribute(sage_gemm<128, true>,
                         cudaFuncAttributeMaxDynamicSharedMemorySize, SMEM2);

    const int gemm_blocks = (n + 63) / 64;

    // ---------------- Layer 1 ----------------
    cudaMemsetAsync(aggp, 0, (size_t)n * 64 * sizeof(float));
    cudaMemsetAsync(statp, 0, 8192 * sizeof(float));
    {
        int total = E * 16;  // whole 64-wide row, one pass (WS ~102MB fits L2)
        sage_scatter<64, 16, false><<<(total + 255) / 256, 256>>>(x, ei, E, agg, 0);
    }
    sage_gemm<64, false><<<gemm_blocks, 256, SMEM1>>>(agg, x, W1l, W1r, b1, h1, n);
    bn_finalize<<<1, 128>>>(g1, be1, 1.0f / (float)n);

    // ---------------- Layer 2 ----------------
    cudaMemsetAsync(aggp, 0, (size_t)n * 128 * sizeof(float));
    cudaMemsetAsync(statp, 0, 8192 * sizeof(float));
    {
        int total = E * 16;  // half-row per pass: WS = 51MB(h1) + 51MB(agg) in L2
        sage_scatter<128, 16, true><<<(total + 255) / 256, 256>>>(h1, ei, E, agg, 0);
        sage_scatter<128, 16, true><<<(total + 255) / 256, 256>>>(h1, ei, E, agg, 64);
    }
    sage_gemm<128, true><<<gemm_blocks, 256, SMEM2>>>(agg, h1, W2l, W2r, b2, out, n);
    bn_finalize<<<1, 128>>>(g2, be2, 1.0f / (float)n);
    bn_apply_relu<<<((n * 32) + 255) / 256, 256>>>(out, n * 32);
}

// round 4
// speedup vs baseline: 1.4721x; 1.3030x over previous
#include <cuda_runtime.h>
#include <cuda_bf16.h>
#include <cstdint>

typedef unsigned long long u64;

#define MAXN 200704
// layer1 agg uses [0, n*64); layer2 agg uses [MAXN*64, MAXN*64 + n*128)
__device__ float g_agg[(size_t)MAXN * 192];
__device__ float g_h1[(size_t)MAXN * 128];
__device__ float g_stats[16384];   // layer L at offset L*8192: [sum 128x32][sq 128x32]
__device__ float g_scale[128];
__device__ float g_shift[128];

__device__ __forceinline__ void red_add4(float* p, float4 v) {
    asm volatile("red.global.add.v4.f32 [%0], {%1,%2,%3,%4};"
                 :: "l"(p), "f"(v.x), "f"(v.y), "f"(v.z), "f"(v.w)
                 : "memory");
}
__device__ __forceinline__ void ffma2(u64& d, u64 a, u64 b) {
    asm("fma.rn.f32x2 %0, %1, %2, %0;" : "+l"(d) : "l"(a), "l"(b));
}
__device__ __forceinline__ u64 pack2(float x) {
    u64 r;
    asm("mov.b64 %0, {%1, %1};" : "=l"(r) : "f"(x));
    return r;
}
__device__ __forceinline__ float2 unpack2(u64 v) {
    float2 f;
    asm("mov.b64 {%0, %1}, %2;" : "=f"(f.x), "=f"(f.y) : "l"(v));
    return f;
}

// ---------------------------------------------------------------------------
// Scatter span of SPANQ*4 features from f_lo: agg[dst] += bn?(feat[src])
// ---------------------------------------------------------------------------
template <int F, int SPANQ, bool BN>
__global__ void sage_scatter(const float* __restrict__ feat,
                             const int* __restrict__ ei,
                             int E, float* __restrict__ aggout, int f_lo) {
    int t = blockIdx.x * blockDim.x + threadIdx.x;
    if (t >= E * SPANQ) return;
    int e  = t / SPANQ;
    int f4 = f_lo + (t - e * SPANQ) * 4;
    int s = ei[e];
    int d = ei[E + e];
    float4 v = *(const float4*)(feat + (size_t)s * F + f4);
    if (BN) {
        float4 sc = *(const float4*)(g_scale + f4);
        float4 sh = *(const float4*)(g_shift + f4);
        v.x = fmaf(v.x, sc.x, sh.x);
        v.y = fmaf(v.y, sc.y, sh.y);
        v.z = fmaf(v.z, sc.z, sh.z);
        v.w = fmaf(v.w, sc.w, sh.w);
    }
    red_add4(aggout + (size_t)d * F + f4, v);
}

// ---------------------------------------------------------------------------
// Fused dual GEMM + bias + relu + BN-stat partials (packed f32x2 FMA).
// 64 rows x 128 cols / 256-thread block. Lane (tid&15) owns cols
// {lane*4..+3} and {64+lane*4..+3} -> conflict-free contiguous weight LDS.128.
// ---------------------------------------------------------------------------
template <int K, bool BNX>
__global__ void __launch_bounds__(256, 2)
sage_gemm(const float* __restrict__ agg,
          const float* __restrict__ xin,
          const float* __restrict__ Wl,
          const float* __restrict__ Wr,
          const float* __restrict__ bias,
          float* __restrict__ out, float* __restrict__ stats, int n) {
    extern __shared__ float smem[];
    float* sWl = smem;                 // K*128
    float* sWr = smem + K * 128;       // K*128
    float* sA  = smem + 2 * K * 128;   // 64*K
    float* sX  = sA + 64 * K;          // 64*K

    const int tid  = threadIdx.x;
    const int row0 = blockIdx.x * 64;

    for (int i = tid * 4; i < K * 128; i += 1024) {
        *(float4*)(sWl + i) = *(const float4*)(Wl + i);
        *(float4*)(sWr + i) = *(const float4*)(Wr + i);
    }
    for (int i = tid * 4; i < 64 * K; i += 1024) {
        int r = i / K, c = i - r * K;
        int gr = row0 + r;
        float4 av = make_float4(0.f, 0.f, 0.f, 0.f);
        float4 xv = av;
        if (gr < n) {
            av = *(const float4*)(agg + (size_t)gr * K + c);
            xv = *(const float4*)(xin + (size_t)gr * K + c);
            if (BNX) {
                float4 sc = *(const float4*)(g_scale + c);
                float4 sh = *(const float4*)(g_shift + c);
                xv.x = fmaf(xv.x, sc.x, sh.x);
                xv.y = fmaf(xv.y, sc.y, sh.y);
                xv.z = fmaf(xv.z, sc.z, sh.z);
                xv.w = fmaf(xv.w, sc.w, sh.w);
            }
        }
        *(float4*)(sA + i) = av;
        *(float4*)(sX + i) = xv;
    }
    __syncthreads();

    const int lane = tid & 15;
    const int rgrp = tid >> 4;
    const int r0   = rgrp * 4;
    const int colA = lane * 4;
    const int colB = 64 + lane * 4;

    u64 acc[4][4];
#pragma unroll
    for (int r = 0; r < 4; r++)
#pragma unroll
        for (int p = 0; p < 4; p++) acc[r][p] = 0ull;

    for (int k = 0; k < K; k += 4) {
        float4 a4[4], x4[4];
#pragma unroll
        for (int r = 0; r < 4; r++) {
            a4[r] = *(float4*)(sA + (r0 + r) * K + k);
            x4[r] = *(float4*)(sX + (r0 + r) * K + k);
        }
#pragma unroll
        for (int kk = 0; kk < 4; kk++) {
            const ulonglong2 wla = *(const ulonglong2*)(sWl + (k + kk) * 128 + colA);
            const ulonglong2 wlb = *(const ulonglong2*)(sWl + (k + kk) * 128 + colB);
            const ulonglong2 wra = *(const ulonglong2*)(sWr + (k + kk) * 128 + colA);
            const ulonglong2 wrb = *(const ulonglong2*)(sWr + (k + kk) * 128 + colB);
#pragma unroll
            for (int r = 0; r < 4; r++) {
                const u64 a2 = pack2((&a4[r].x)[kk]);
                const u64 b2 = pack2((&x4[r].x)[kk]);
                ffma2(acc[r][0], a2, wla.x); ffma2(acc[r][0], b2, wra.x);
                ffma2(acc[r][1], a2, wla.y); ffma2(acc[r][1], b2, wra.y);
                ffma2(acc[r][2], a2, wlb.x); ffma2(acc[r][2], b2, wrb.x);
                ffma2(acc[r][3], a2, wlb.y); ffma2(acc[r][3], b2, wrb.y);
            }
        }
    }

    float bs[8];
#pragma unroll
    for (int c = 0; c < 4; c++) {
        bs[c]     = bias[colA + c];
        bs[4 + c] = bias[colB + c];
    }

    __syncthreads();                 // reuse sA as reduction buffer
    float* redS = sA;                // 16*128
    float* redQ = sA + 2048;         // 16*128

    float psum[8], psq[8];
#pragma unroll
    for (int c = 0; c < 8; c++) { psum[c] = 0.f; psq[c] = 0.f; }

#pragma unroll
    for (int r = 0; r < 4; r++) {
        int gr = row0 + r0 + r;
        if (gr >= n) continue;
        float v[8];
#pragma unroll
        for (int p = 0; p < 4; p++) {
            float2 f = unpack2(acc[r][p]);
            v[p * 2]     = f.x;
            v[p * 2 + 1] = f.y;
        }
#pragma unroll
        for (int c = 0; c < 8; c++) {
            float tval = fmaxf(v[c] + bs[c], 0.f);
            v[c] = tval;
            psum[c] += tval;
            psq[c]  += tval * tval;
        }
        float4* opA = (float4*)(out + (size_t)gr * 128 + colA);
        float4* opB = (float4*)(out + (size_t)gr * 128 + colB);
        *opA = make_float4(v[0], v[1], v[2], v[3]);
        *opB = make_float4(v[4], v[5], v[6], v[7]);
    }

#pragma unroll
    for (int c = 0; c < 4; c++) {
        redS[rgrp * 128 + colA + c] = psum[c];
        redS[rgrp * 128 + colB + c] = psum[4 + c];
        redQ[rgrp * 128 + colA + c] = psq[c];
        redQ[rgrp * 128 + colB + c] = psq[4 + c];
    }
    __syncthreads();
    if (tid < 128) {
        float s = 0.f, q = 0.f;
#pragma unroll
        for (int g = 0; g < 16; g++) {
            s += redS[g * 128 + tid];
            q += redQ[g * 128 + tid];
        }
        int slot = blockIdx.x & 31;
        atomicAdd(&stats[tid * 32 + slot], s);
        atomicAdd(&stats[4096 + tid * 32 + slot], q);
    }
}

__global__ void bn_finalize(const float* __restrict__ gamma,
                            const float* __restrict__ beta,
                            const float* __restrict__ stats, float inv_n) {
    int c = threadIdx.x;  // 128 threads
    float s = 0.f, q = 0.f;
#pragma unroll
    for (int j = 0; j < 32; j++) {
        s += stats[c * 32 + j];
        q += stats[4096 + c * 32 + j];
    }
    float mu  = s * inv_n;
    float var = q * inv_n - mu * mu;
    float sc  = gamma[c] * rsqrtf(var + 1e-5f);
    g_scale[c] = sc;
    g_shift[c] = beta[c] - mu * sc;
}

__global__ void bn_apply_relu(float* __restrict__ out, int total4) {
    int i = blockIdx.x * blockDim.x + threadIdx.x;
    if (i >= total4) return;
    float4 v = ((float4*)out)[i];
    int c = (i & 31) * 4;
    float4 sc = *(const float4*)(g_scale + c);
    float4 sh = *(const float4*)(g_shift + c);
    v.x = fmaxf(fmaf(v.x, sc.x, sh.x), 0.f);
    v.y = fmaxf(fmaf(v.y, sc.y, sh.y), 0.f);
    v.z = fmaxf(fmaf(v.z, sc.z, sh.z), 0.f);
    v.w = fmaxf(fmaf(v.w, sc.w, sh.w), 0.f);
    ((float4*)out)[i] = v;
}

// ---------------------------------------------------------------------------
extern "C" void kernel_launch(void* const* d_in, const int* in_sizes, int n_in,
                              void* d_out, int out_size) {
    const float* x   = (const float*)d_in[0];
    const int*   ei  = (const int*)d_in[1];
    const float* W1l = (const float*)d_in[2];
    const float* b1  = (const float*)d_in[3];
    const float* W1r = (const float*)d_in[4];
    const float* g1  = (const float*)d_in[5];
    const float* be1 = (const float*)d_in[6];
    const float* W2l = (const float*)d_in[7];
    const float* b2  = (const float*)d_in[8];
    const float* W2r = (const float*)d_in[9];
    const float* g2  = (const float*)d_in[10];
    const float* be2 = (const float*)d_in[11];
    float* out = (float*)d_out;

    const int n = in_sizes[0] / 64;
    const int E = in_sizes[1] / 2;

    void *aggp, *h1p, *statp, *scalep;
    cudaGetSymbolAddress(&aggp, g_agg);
    cudaGetSymbolAddress(&h1p, g_h1);
    cudaGetSymbolAddress(&statp, g_stats);
    cudaGetSymbolAddress(&scalep, g_scale);
    float* agg1   = (float*)aggp;
    float* agg2   = (float*)aggp + (size_t)MAXN * 64;
    float* h1     = (float*)h1p;
    float* stats1 = (float*)statp;
    float* stats2 = (float*)statp + 8192;

    const int SMEM1 = (2 * 64 * 128 + 2 * 64 * 64) * 4;    // 96 KB
    const int SMEM2 = (2 * 128 * 128 + 2 * 64 * 128) * 4;  // 192 KB
    cudaFuncSetAttribute(sage_gemm<64, false>,
                         cudaFuncAttributeMaxDynamicSharedMemorySize, SMEM1);
    cudaFuncSetAttribute(sage_gemm<128, true>,
                         cudaFuncAttributeMaxDynamicSharedMemorySize, SMEM2);

    const int gemm_blocks = (n + 63) / 64;

    // Upfront clears (also aligns ncu skip window so a GEMM gets captured)
    cudaMemsetAsync(aggp, 0, ((size_t)MAXN * 64 + (size_t)n * 128) * sizeof(float));
    cudaMemsetAsync(statp, 0, 16384 * sizeof(float));
    cudaMemsetAsync(scalep, 0, 128 * sizeof(float));   // dummy (overwritten by bnf1)

    // ---------------- Layer 1 ----------------
    {
        int total = E * 8;   // half-row (32 feats) per pass: L2-resident WS
        sage_scatter<64, 8, false><<<(total + 255) / 256, 256>>>(x, ei, E, agg1, 0);
        sage_scatter<64, 8, false><<<(total + 255) / 256, 256>>>(x, ei, E, agg1, 32);
    }
    sage_gemm<64, false><<<gemm_blocks, 256, SMEM1>>>(agg1, x, W1l, W1r, b1, h1, stats1, n);
    bn_finalize<<<1, 128>>>(g1, be1, stats1, 1.0f / (float)n);

    // ---------------- Layer 2 ----------------
    {
        int total = E * 16;  // half-row (64 feats) per pass
        sage_scatter<128, 16, true><<<(total + 255) / 256, 256>>>(h1, ei, E, agg2, 0);
        sage_scatter<128, 16, true><<<(total + 255) / 256, 256>>>(h1, ei, E, agg2, 64);
    }
    sage_gemm<128, true><<<gemm_blocks, 256, SMEM2>>>(agg2, h1, W2l, W2r, b2, out, stats2, n);
    bn_finalize<<<1, 128>>>(g2, be2, stats2, 1.0f / (float)n);
    bn_apply_relu<<<((n * 32) + 255) / 256, 256>>>(out, n * 32);
}

// round 6
// speedup vs baseline: 1.6611x; 1.1284x over previous
#include <cuda_runtime.h>
#include <cstdint>

typedef unsigned long long u64;

#define MAXN 200704
__device__ float g_agg[(size_t)MAXN * 192];
__device__ float g_h1[(size_t)MAXN * 128];
__device__ float g_deg[MAXN];
__device__ float g_w2p[32768];     // folded W2l' then W2r' (each 128x128)
__device__ float g_uv[256];        // u[128] = t@W2l ; v[128] = t@W2r
__device__ float g_stats[16384];   // layer L at L*8192: [sum 128x32][sq 128x32]
__device__ float g_scale[128];
__device__ float g_shift[128];

// ---------------------------------------------------------------------------
__device__ __forceinline__ void red_add4(float* p, float4 v) {
    asm volatile("red.global.add.v4.f32 [%0], {%1,%2,%3,%4};"
                 :: "l"(p), "f"(v.x), "f"(v.y), "f"(v.z), "f"(v.w) : "memory");
}
__device__ __forceinline__ void red_add1(float* p, float v) {
    asm volatile("red.global.add.f32 [%0], %1;" :: "l"(p), "f"(v) : "memory");
}
__device__ __forceinline__ void ffma2(u64& d, u64 a, u64 b) {
    asm("fma.rn.f32x2 %0, %1, %2, %0;" : "+l"(d) : "l"(a), "l"(b));
}
__device__ __forceinline__ u64 pack2(float x) {
    u64 r;
    asm("mov.b64 %0, {%1, %1};" : "=l"(r) : "f"(x));
    return r;
}
__device__ __forceinline__ float2 unpack2(u64 v) {
    float2 f;
    asm("mov.b64 {%0, %1}, %2;" : "=f"(f.x), "=f"(f.y) : "l"(v));
    return f;
}
__device__ __forceinline__ void cp16(uint32_t dst, const void* src, bool pred) {
    asm volatile("cp.async.cg.shared.global [%0], [%1], 16, %2;"
                 :: "r"(dst), "l"(src), "r"(pred ? 16 : 0) : "memory");
}
#define CP_COMMIT() asm volatile("cp.async.commit_group;" ::: "memory")
#define CP_WAIT(N)  asm volatile("cp.async.wait_group %0;" :: "n"(N) : "memory")

// ---------------------------------------------------------------------------
// Scatter: agg[dst, f_lo..] += feat[src, f_lo..] over SPANQ*4 features
// ---------------------------------------------------------------------------
template <int F, int SPANQ>
__global__ void sage_scatter(const float* __restrict__ feat,
                             const int* __restrict__ ei,
                             int E, float* __restrict__ aggout, int f_lo) {
    int t = blockIdx.x * blockDim.x + threadIdx.x;
    if (t >= E * SPANQ) return;
    int e  = t / SPANQ;
    int f4 = f_lo + (t - e * SPANQ) * 4;
    int s = ei[e];
    int d = ei[E + e];
    float4 v = *(const float4*)(feat + (size_t)s * F + f4);
    red_add4(aggout + (size_t)d * F + f4, v);
}

__global__ void compute_deg(const int* __restrict__ ei, int E, float* __restrict__ deg) {
    int e = blockIdx.x * blockDim.x + threadIdx.x;
    if (e >= E) return;
    red_add1(&deg[ei[E + e]], 1.0f);
}

// Fold BN1 into layer-2 weights: W' = diag(s)W ; u = t@W2l ; v = t@W2r
__global__ void prep_layer2(const float* __restrict__ W2l,
                            const float* __restrict__ W2r,
                            float* __restrict__ W2lp, float* __restrict__ W2rp,
                            float* __restrict__ uv) {
    int nidx = threadIdx.x & 127;
    int ko   = threadIdx.x >> 7;            // 0..1
    int kb   = blockIdx.x * 8;              // 16 blocks x 8 k-rows
    float usum = 0.f, vsum = 0.f;
#pragma unroll
    for (int i = 0; i < 4; i++) {
        int k = kb + i * 2 + ko;
        float s = g_scale[k], t = g_shift[k];
        float wl = W2l[k * 128 + nidx];
        float wr = W2r[k * 128 + nidx];
        W2lp[k * 128 + nidx] = wl * s;
        W2rp[k * 128 + nidx] = wr * s;
        usum += t * wl;
        vsum += t * wr;
    }
    red_add1(&uv[nidx], usum);
    red_add1(&uv[128 + nidx], vsum);
}

// ---------------------------------------------------------------------------
// Persistent dual GEMM (packed f32x2), cp.async double-buffered 32-k chunks.
// out[r,:] = relu(agg[r,:]@Wl + xin[r,:]@Wr + add_r), where
//   add_r = bias (DEG=false)  or  (b2+v) + deg[r]*u (DEG=true, folded BN).
// Tile 64 rows x 128 cols; lane owns cols {l*4..+3, 64+l*4..+3} (conflict-free).
// ---------------------------------------------------------------------------
template <int K, bool DEG>
__global__ void __launch_bounds__(256, DEG ? 1 : 2)
sage_gemm_p(const float* __restrict__ agg,
            const float* __restrict__ xin,
            const float* __restrict__ Wl,
            const float* __restrict__ Wr,
            const float* __restrict__ bias,
            const float* __restrict__ uv,
            const float* __restrict__ deg,
            float* __restrict__ out, float* __restrict__ stats,
            int n, int ntiles) {
    extern __shared__ float smem[];
    float* sWl = smem;                     // K*128
    float* sWr = smem + K * 128;           // K*128
    float* chf = smem + 2 * K * 128;       // 4 x 2048 floats: A0,X0,A1,X1
    const uint32_t chb = (uint32_t)__cvta_generic_to_shared(chf);
    constexpr int NCH = K / 32;

    const int tid  = threadIdx.x;
    const int lane = tid & 15;
    const int rgrp = tid >> 4;
    const int r0   = rgrp * 4;
    const int colA = lane * 4;
    const int colB = 64 + lane * 4;

    // Stage weights once
    for (int i = tid * 4; i < K * 128; i += 1024) {
        *(float4*)(sWl + i) = *(const float4*)(Wl + i);
        *(float4*)(sWr + i) = *(const float4*)(Wr + i);
    }
    __syncthreads();

    // Per-thread epilogue constants
    float bs[8], us[8];
#pragma unroll
    for (int c = 0; c < 4; c++) {
        int ca = colA + c, cb2 = colB + c;
        if (DEG) {
            bs[c]     = bias[ca]  + uv[128 + ca];
            bs[4 + c] = bias[cb2] + uv[128 + cb2];
            us[c]     = uv[ca];
            us[4 + c] = uv[cb2];
        } else {
            bs[c]     = bias[ca];
            bs[4 + c] = bias[cb2];
        }
    }

    // cp.async segment mapping: 512 x 16B per chunk per matrix
    const int seg0 = tid * 2;

    for (int tile = blockIdx.x; tile < ntiles; tile += gridDim.x) {
        const int row0 = tile << 6;

        // prefetch chunk 0
        {
#pragma unroll
            for (int j = 0; j < 2; j++) {
                int seg = seg0 + j, r = seg >> 3, s8 = seg & 7;
                int gr = row0 + r;
                bool p = gr < n;
                const float* sa = agg + (size_t)gr * K + s8 * 4;
                const float* sx = xin + (size_t)gr * K + s8 * 4;
                uint32_t d = chb + (uint32_t)(r * 32 + s8 * 4) * 4;
                cp16(d, sa, p);
                cp16(d + 8192, sx, p);
            }
            CP_COMMIT();
        }

        u64 acc[4][4];
#pragma unroll
        for (int r = 0; r < 4; r++)
#pragma unroll
            for (int p = 0; p < 4; p++) acc[r][p] = 0ull;

        for (int c = 0; c < NCH; c++) {
            const int b = c & 1;
            if (c + 1 < NCH) {
                const int k0n = (c + 1) * 32, bn = (c + 1) & 1;
#pragma unroll
                for (int j = 0; j < 2; j++) {
                    int seg = seg0 + j, r = seg >> 3, s8 = seg & 7;
                    int gr = row0 + r;
                    bool p = gr < n;
                    const float* sa = agg + (size_t)gr * K + k0n + s8 * 4;
                    const float* sx = xin + (size_t)gr * K + k0n + s8 * 4;
                    uint32_t d = chb + (uint32_t)bn * 16384 + (uint32_t)(r * 32 + s8 * 4) * 4;
                    cp16(d, sa, p);
                    cp16(d + 8192, sx, p);
                }
                CP_COMMIT();
                CP_WAIT(1);
            } else {
                CP_WAIT(0);
            }
            __syncthreads();

            const float* sA = chf + b * 4096;
            const float* sX = sA + 2048;
            const int kw0 = c * 32;
#pragma unroll 2
            for (int k = 0; k < 32; k += 4) {
                float4 a4[4], x4[4];
#pragma unroll
                for (int r = 0; r < 4; r++) {
                    a4[r] = *(const float4*)(sA + (r0 + r) * 32 + k);
                    x4[r] = *(const float4*)(sX + (r0 + r) * 32 + k);
                }
#pragma unroll
                for (int kk = 0; kk < 4; kk++) {
                    const int kw = (kw0 + k + kk) * 128;
                    const ulonglong2 wla = *(const ulonglong2*)(sWl + kw + colA);
                    const ulonglong2 wlb = *(const ulonglong2*)(sWl + kw + colB);
                    const ulonglong2 wra = *(const ulonglong2*)(sWr + kw + colA);
                    const ulonglong2 wrb = *(const ulonglong2*)(sWr + kw + colB);
#pragma unroll
                    for (int r = 0; r < 4; r++) {
                        const u64 a2 = pack2((&a4[r].x)[kk]);
                        const u64 b2 = pack2((&x4[r].x)[kk]);
                        ffma2(acc[r][0], a2, wla.x); ffma2(acc[r][0], b2, wra.x);
                        ffma2(acc[r][1], a2, wla.y); ffma2(acc[r][1], b2, wra.y);
                        ffma2(acc[r][2], a2, wlb.x); ffma2(acc[r][2], b2, wrb.x);
                        ffma2(acc[r][3], a2, wlb.y); ffma2(acc[r][3], b2, wrb.y);
                    }
                }
            }
            __syncthreads();
        }

        // ---- epilogue: bias(+deg*u), relu, store, BN stats ----
        float* redS = chf;          // 16*128
        float* redQ = chf + 2048;   // 16*128
        float psum[8], psq[8];
#pragma unroll
        for (int c = 0; c < 8; c++) { psum[c] = 0.f; psq[c] = 0.f; }

#pragma unroll
        for (int r = 0; r < 4; r++) {
            int gr = row0 + r0 + r;
            if (gr >= n) continue;
            float dg = DEG ? deg[gr] : 0.f;
            float v[8];
#pragma unroll
            for (int p = 0; p < 4; p++) {
                float2 f = unpack2(acc[r][p]);
                v[p * 2]     = f.x;
                v[p * 2 + 1] = f.y;
            }
#pragma unroll
            for (int c = 0; c < 8; c++) {
                float add = DEG ? (bs[c] + dg * us[c]) : bs[c];
                float tval = fmaxf(v[c] + add, 0.f);
                v[c] = tval;
                psum[c] += tval;
                psq[c]  += tval * tval;
            }
            *(float4*)(out + (size_t)gr * 128 + colA) = make_float4(v[0], v[1], v[2], v[3]);
            *(float4*)(out + (size_t)gr * 128 + colB) = make_float4(v[4], v[5], v[6], v[7]);
        }

#pragma unroll
        for (int c = 0; c < 4; c++) {
            redS[rgrp * 128 + colA + c] = psum[c];
            redS[rgrp * 128 + colB + c] = psum[4 + c];
            redQ[rgrp * 128 + colA + c] = psq[c];
            redQ[rgrp * 128 + colB + c] = psq[4 + c];
        }
        __syncthreads();
        if (tid < 128) {
            float s = 0.f, q = 0.f;
#pragma unroll
            for (int g = 0; g < 16; g++) {
                s += redS[g * 128 + tid];
                q += redQ[g * 128 + tid];
            }
            int slot = tile & 31;
            red_add1(&stats[tid * 32 + slot], s);
            red_add1(&stats[4096 + tid * 32 + slot], q);
        }
        __syncthreads();
    }
}

// ---------------------------------------------------------------------------
__global__ void bn_finalize(const float* __restrict__ gamma,
                            const float* __restrict__ beta,
                            const float* __restrict__ stats, float inv_n) {
    int c = threadIdx.x;  // 128 threads
    float s = 0.f, q = 0.f;
#pragma unroll
    for (int j = 0; j < 32; j++) {
        s += stats[c * 32 + j];
        q += stats[4096 + c * 32 + j];
    }
    float mu  = s * inv_n;
    float var = q * inv_n - mu * mu;
    float sc  = gamma[c] * rsqrtf(var + 1e-5f);
    g_scale[c] = sc;
    g_shift[c] = beta[c] - mu * sc;
}

__global__ void bn_apply_relu(float* __restrict__ out, int total4) {
    int i = blockIdx.x * blockDim.x + threadIdx.x;
    if (i >= total4) return;
    float4 v = ((float4*)out)[i];
    int c = (i & 31) * 4;
    float4 sc = *(const float4*)(g_scale + c);
    float4 sh = *(const float4*)(g_shift + c);
    v.x = fmaxf(fmaf(v.x, sc.x, sh.x), 0.f);
    v.y = fmaxf(fmaf(v.y, sc.y, sh.y), 0.f);
    v.z = fmaxf(fmaf(v.z, sc.z, sh.z), 0.f);
    v.w = fmaxf(fmaf(v.w, sc.w, sh.w), 0.f);
    ((float4*)out)[i] = v;
}

// ---------------------------------------------------------------------------
extern "C" void kernel_launch(void* const* d_in, const int* in_sizes, int n_in,
                              void* d_out, int out_size) {
    const float* x   = (const float*)d_in[0];
    const int*   ei  = (const int*)d_in[1];
    const float* W1l = (const float*)d_in[2];
    const float* b1  = (const float*)d_in[3];
    const float* W1r = (const float*)d_in[4];
    const float* g1  = (const float*)d_in[5];
    const float* be1 = (const float*)d_in[6];
    const float* W2l = (const float*)d_in[7];
    const float* b2  = (const float*)d_in[8];
    const float* W2r = (const float*)d_in[9];
    const float* g2  = (const float*)d_in[10];
    const float* be2 = (const float*)d_in[11];
    float* out = (float*)d_out;

    const int n = in_sizes[0] / 64;
    const int E = in_sizes[1] / 2;

    void *aggp, *h1p, *statp, *degp, *w2pp, *uvp;
    cudaGetSymbolAddress(&aggp, g_agg);
    cudaGetSymbolAddress(&h1p, g_h1);
    cudaGetSymbolAddress(&statp, g_stats);
    cudaGetSymbolAddress(&degp, g_deg);
    cudaGetSymbolAddress(&w2pp, g_w2p);
    cudaGetSymbolAddress(&uvp, g_uv);
    float* agg1   = (float*)aggp;
    float* agg2   = (float*)aggp + (size_t)MAXN * 64;
    float* h1     = (float*)h1p;
    float* stats1 = (float*)statp;
    float* stats2 = (float*)statp + 8192;
    float* deg    = (float*)degp;
    float* W2lp   = (float*)w2pp;
    float* W2rp   = (float*)w2pp + 16384;
    float* uv     = (float*)uvp;

    const int SMEM1 = 2 * 64 * 128 * 4 + 32768;    // 96 KB
    const int SMEM2 = 2 * 128 * 128 * 4 + 32768;   // 160 KB
    cudaFuncSetAttribute(sage_gemm_p<64, false>,
                         cudaFuncAttributeMaxDynamicSharedMemorySize, SMEM1);
    cudaFuncSetAttribute(sage_gemm_p<128, true>,
                         cudaFuncAttributeMaxDynamicSharedMemorySize, SMEM2);

    const int ntiles = (n + 63) / 64;

    // Upfront clears
    cudaMemsetAsync(aggp, 0, ((size_t)MAXN * 64 + (size_t)n * 128) * sizeof(float));
    cudaMemsetAsync(statp, 0, 16384 * sizeof(float));
    cudaMemsetAsync(degp, 0, (size_t)n * sizeof(float));
    cudaMemsetAsync(uvp, 0, 256 * sizeof(float));

    compute_deg<<<(E + 255) / 256, 256>>>(ei, E, deg);

    // ---------------- Layer 1 ----------------
    {
        int total = E * 8;
        sage_scatter<64, 8><<<(total + 255) / 256, 256>>>(x, ei, E, agg1, 0);
        sage_scatter<64, 8><<<(total + 255) / 256, 256>>>(x, ei, E, agg1, 32);
    }
    sage_gemm_p<64, false><<<296, 256, SMEM1>>>(agg1, x, W1l, W1r, b1,
                                                nullptr, nullptr, h1, stats1, n, ntiles);
    bn_finalize<<<1, 128>>>(g1, be1, stats1, 1.0f / (float)n);
    prep_layer2<<<16, 256>>>(W2l, W2r, W2lp, W2rp, uv);

    // ---------------- Layer 2 ----------------
    {
        int total = E * 16;
        sage_scatter<128, 16><<<(total + 255) / 256, 256>>>(h1, ei, E, agg2, 0);
        sage_scatter<128, 16><<<(total + 255) / 256, 256>>>(h1, ei, E, agg2, 64);
    }
    sage_gemm_p<128, true><<<148, 256, SMEM2>>>(agg2, h1, W2lp, W2rp, b2,
                                                uv, deg, out, stats2, n, ntiles);
    bn_finalize<<<1, 128>>>(g2, be2, stats2, 1.0f / (float)n);
    bn_apply_relu<<<((n * 32) + 255) / 256, 256>>>(out, n * 32);
}

// round 7
// speedup vs baseline: 1.6955x; 1.0207x over previous
#include <cuda_runtime.h>
#include <cstdint>

typedef unsigned long long u64;

#define MAXN 200704
__device__ float g_agg[(size_t)MAXN * 192];
__device__ float g_h1[(size_t)MAXN * 128];
__device__ float g_deg[MAXN];
__device__ float g_w2p[32768];     // folded W2l' then W2r' (each 128x128)
__device__ float g_uv[256];        // u[128] = t@W2l ; v[128] = t@W2r
__device__ float g_stats[16384];   // layer L at L*8192: [sum 128x32][sq 128x32]
__device__ float g_scale[128];
__device__ float g_shift[128];

// ---------------------------------------------------------------------------
__device__ __forceinline__ void red_add4(float* p, float4 v) {
    asm volatile("red.global.add.v4.f32 [%0], {%1,%2,%3,%4};"
                 :: "l"(p), "f"(v.x), "f"(v.y), "f"(v.z), "f"(v.w) : "memory");
}
__device__ __forceinline__ void red_add1(float* p, float v) {
    asm volatile("red.global.add.f32 [%0], %1;" :: "l"(p), "f"(v) : "memory");
}
__device__ __forceinline__ void ffma2(u64& d, u64 a, u64 b) {
    asm("fma.rn.f32x2 %0, %1, %2, %0;" : "+l"(d) : "l"(a), "l"(b));
}
__device__ __forceinline__ u64 pack2(float x) {
    u64 r;
    asm("mov.b64 %0, {%1, %1};" : "=l"(r) : "f"(x));
    return r;
}
__device__ __forceinline__ float2 unpack2(u64 v) {
    float2 f;
    asm("mov.b64 {%0, %1}, %2;" : "=f"(f.x), "=f"(f.y) : "l"(v));
    return f;
}
__device__ __forceinline__ void cp16(uint32_t dst, const void* src, bool pred) {
    asm volatile("cp.async.cg.shared.global [%0], [%1], 16, %2;"
                 :: "r"(dst), "l"(src), "r"(pred ? 16 : 0) : "memory");
}
#define CP_COMMIT() asm volatile("cp.async.commit_group;" ::: "memory")
#define CP_WAIT(N)  asm volatile("cp.async.wait_group %0;" :: "n"(N) : "memory")

// ---------------------------------------------------------------------------
// Scatter: agg[dst, f_lo..] += feat[src, f_lo..] over SPANQ*4 features
// ---------------------------------------------------------------------------
template <int F, int SPANQ>
__global__ void sage_scatter(const float* __restrict__ feat,
                             const int* __restrict__ ei,
                             int E, float* __restrict__ aggout, int f_lo) {
    int t = blockIdx.x * blockDim.x + threadIdx.x;
    if (t >= E * SPANQ) return;
    int e  = t / SPANQ;
    int f4 = f_lo + (t - e * SPANQ) * 4;
    int s = ei[e];
    int d = ei[E + e];
    float4 v = *(const float4*)(feat + (size_t)s * F + f4);
    red_add4(aggout + (size_t)d * F + f4, v);
}

__global__ void compute_deg(const int* __restrict__ ei, int E, float* __restrict__ deg) {
    int e = blockIdx.x * blockDim.x + threadIdx.x;
    if (e >= E) return;
    red_add1(&deg[ei[E + e]], 1.0f);
}

// Fold BN1 into layer-2 weights: W' = diag(s)W ; u = t@W2l ; v = t@W2r
__global__ void prep_layer2(const float* __restrict__ W2l,
                            const float* __restrict__ W2r,
                            float* __restrict__ W2lp, float* __restrict__ W2rp,
                            float* __restrict__ uv) {
    int nidx = threadIdx.x & 127;
    int ko   = threadIdx.x >> 7;            // 0..1
    int kb   = blockIdx.x * 8;              // 16 blocks x 8 k-rows
    float usum = 0.f, vsum = 0.f;
#pragma unroll
    for (int i = 0; i < 4; i++) {
        int k = kb + i * 2 + ko;
        float s = g_scale[k], t = g_shift[k];
        float wl = W2l[k * 128 + nidx];
        float wr = W2r[k * 128 + nidx];
        W2lp[k * 128 + nidx] = wl * s;
        W2rp[k * 128 + nidx] = wr * s;
        usum += t * wl;
        vsum += t * wr;
    }
    red_add1(&uv[nidx], usum);
    red_add1(&uv[128 + nidx], vsum);
}

// ---------------------------------------------------------------------------
// Persistent dual GEMM (packed f32x2), 512 threads, 128x128 tile,
// cp.async double-buffered 32-k chunks.
// out[r,:] = relu(agg[r,:]@Wl + xin[r,:]@Wr + add_r), where
//   add_r = bias (DEG=false)  or  (b2+v) + deg[r]*u (DEG=true, folded BN1).
// Lane (tid&15) owns cols {l*4..+3, 64+l*4..+3}: conflict-free LDS.128.
// ---------------------------------------------------------------------------
template <int K, bool DEG>
__global__ void __launch_bounds__(512, 1)
sage_gemm_p(const float* __restrict__ agg,
            const float* __restrict__ xin,
            const float* __restrict__ Wl,
            const float* __restrict__ Wr,
            const float* __restrict__ bias,
            const float* __restrict__ uv,
            const float* __restrict__ deg,
            float* __restrict__ out, float* __restrict__ stats,
            int n, int ntiles) {
    extern __shared__ float smem[];
    float* sWl = smem;                     // K*128
    float* sWr = smem + K * 128;           // K*128
    float* chf = smem + 2 * K * 128;       // 2 bufs x (A 4096f + X 4096f) = 64KB
    const uint32_t chb = (uint32_t)__cvta_generic_to_shared(chf);
    constexpr int NCH = K / 32;

    const int tid  = threadIdx.x;
    const int lane = tid & 15;
    const int rgrp = tid >> 4;     // 0..31
    const int r0   = rgrp * 4;     // rows r0..r0+3 of 128
    const int colA = lane * 4;
    const int colB = 64 + lane * 4;

    // Stage weights once per SM
    for (int i = tid * 4; i < K * 128; i += 2048) {
        *(float4*)(sWl + i) = *(const float4*)(Wl + i);
        *(float4*)(sWr + i) = *(const float4*)(Wr + i);
    }
    __syncthreads();

    // Per-thread epilogue constants
    float bs[8], us[8];
#pragma unroll
    for (int c = 0; c < 4; c++) {
        int ca = colA + c, cb2 = colB + c;
        if (DEG) {
            bs[c]     = bias[ca]  + uv[128 + ca];
            bs[4 + c] = bias[cb2] + uv[128 + cb2];
            us[c]     = uv[ca];
            us[4 + c] = uv[cb2];
        } else {
            bs[c]     = bias[ca];
            bs[4 + c] = bias[cb2];
        }
    }

    // cp.async: chunk = 128 rows x 32 k = 1024 x 16B segments per matrix
    const int seg0 = tid * 2;

    for (int tile = blockIdx.x; tile < ntiles; tile += gridDim.x) {
        const int row0 = tile << 7;

        // prefetch chunk 0
        {
#pragma unroll
            for (int j = 0; j < 2; j++) {
                int seg = seg0 + j, r = seg >> 3, s8 = seg & 7;
                int gr = row0 + r;
                bool p = gr < n;
                const float* sa = agg + (size_t)gr * K + s8 * 4;
                const float* sx = xin + (size_t)gr * K + s8 * 4;
                uint32_t d = chb + (uint32_t)(r * 32 + s8 * 4) * 4;
                cp16(d, sa, p);
                cp16(d + 16384, sx, p);
            }
            CP_COMMIT();
        }

        u64 acc[4][4];
#pragma unroll
        for (int r = 0; r < 4; r++)
#pragma unroll
            for (int p = 0; p < 4; p++) acc[r][p] = 0ull;

        for (int c = 0; c < NCH; c++) {
            const int b = c & 1;
            if (c + 1 < NCH) {
                const int k0n = (c + 1) * 32, bn = (c + 1) & 1;
#pragma unroll
                for (int j = 0; j < 2; j++) {
                    int seg = seg0 + j, r = seg >> 3, s8 = seg & 7;
                    int gr = row0 + r;
                    bool p = gr < n;
                    const float* sa = agg + (size_t)gr * K + k0n + s8 * 4;
                    const float* sx = xin + (size_t)gr * K + k0n + s8 * 4;
                    uint32_t d = chb + (uint32_t)bn * 32768 + (uint32_t)(r * 32 + s8 * 4) * 4;
                    cp16(d, sa, p);
                    cp16(d + 16384, sx, p);
                }
                CP_COMMIT();
                CP_WAIT(1);
            } else {
                CP_WAIT(0);
            }
            __syncthreads();

            const float* sA = chf + b * 8192;
            const float* sX = sA + 4096;
            const int kw0 = c * 32;
#pragma unroll 2
            for (int k = 0; k < 32; k += 4) {
                float4 a4[4], x4[4];
#pragma unroll
                for (int r = 0; r < 4; r++) {
                    a4[r] = *(const float4*)(sA + (r0 + r) * 32 + k);
                    x4[r] = *(const float4*)(sX + (r0 + r) * 32 + k);
                }
#pragma unroll
                for (int kk = 0; kk < 4; kk++) {
                    const int kw = (kw0 + k + kk) * 128;
                    const ulonglong2 wla = *(const ulonglong2*)(sWl + kw + colA);
                    const ulonglong2 wlb = *(const ulonglong2*)(sWl + kw + colB);
                    const ulonglong2 wra = *(const ulonglong2*)(sWr + kw + colA);
                    const ulonglong2 wrb = *(const ulonglong2*)(sWr + kw + colB);
#pragma unroll
                    for (int r = 0; r < 4; r++) {
                        const u64 a2 = pack2((&a4[r].x)[kk]);
                        const u64 b2 = pack2((&x4[r].x)[kk]);
                        ffma2(acc[r][0], a2, wla.x); ffma2(acc[r][0], b2, wra.x);
                        ffma2(acc[r][1], a2, wla.y); ffma2(acc[r][1], b2, wra.y);
                        ffma2(acc[r][2], a2, wlb.x); ffma2(acc[r][2], b2, wrb.x);
                        ffma2(acc[r][3], a2, wlb.y); ffma2(acc[r][3], b2, wrb.y);
                    }
                }
            }
            __syncthreads();
        }

        // ---- epilogue: bias(+deg*u), relu, store, BN stats ----
        float* redS = chf;          // 32*128 floats
        float* redQ = chf + 4096;   // 32*128 floats
        float psum[8], psq[8];
#pragma unroll
        for (int c = 0; c < 8; c++) { psum[c] = 0.f; psq[c] = 0.f; }

#pragma unroll
        for (int r = 0; r < 4; r++) {
            int gr = row0 + r0 + r;
            if (gr >= n) continue;
            float dg = DEG ? deg[gr] : 0.f;
            float v[8];
#pragma unroll
            for (int p = 0; p < 4; p++) {
                float2 f = unpack2(acc[r][p]);
                v[p * 2]     = f.x;
                v[p * 2 + 1] = f.y;
            }
#pragma unroll
            for (int c = 0; c < 8; c++) {
                float add = DEG ? (bs[c] + dg * us[c]) : bs[c];
                float tval = fmaxf(v[c] + add, 0.f);
                v[c] = tval;
                psum[c] += tval;
                psq[c]  += tval * tval;
            }
            *(float4*)(out + (size_t)gr * 128 + colA) = make_float4(v[0], v[1], v[2], v[3]);
            *(float4*)(out + (size_t)gr * 128 + colB) = make_float4(v[4], v[5], v[6], v[7]);
        }

#pragma unroll
        for (int c = 0; c < 4; c++) {
            redS[rgrp * 128 + colA + c] = psum[c];
            redS[rgrp * 128 + colB + c] = psum[4 + c];
            redQ[rgrp * 128 + colA + c] = psq[c];
            redQ[rgrp * 128 + colB + c] = psq[4 + c];
        }
        __syncthreads();
        if (tid < 128) {
            float s = 0.f, q = 0.f;
#pragma unroll
            for (int g = 0; g < 32; g++) {
                s += redS[g * 128 + tid];
                q += redQ[g * 128 + tid];
            }
            int slot = tile & 31;
            red_add1(&stats[tid * 32 + slot], s);
            red_add1(&stats[4096 + tid * 32 + slot], q);
        }
        __syncthreads();
    }
}

// ---------------------------------------------------------------------------
__global__ void bn_finalize(const float* __restrict__ gamma,
                            const float* __restrict__ beta,
                            const float* __restrict__ stats, float inv_n) {
    int c = threadIdx.x;  // 128 threads
    float s = 0.f, q = 0.f;
#pragma unroll
    for (int j = 0; j < 32; j++) {
        s += stats[c * 32 + j];
        q += stats[4096 + c * 32 + j];
    }
    float mu  = s * inv_n;
    float var = q * inv_n - mu * mu;
    float sc  = gamma[c] * rsqrtf(var + 1e-5f);
    g_scale[c] = sc;
    g_shift[c] = beta[c] - mu * sc;
}

__global__ void bn_apply_relu(float* __restrict__ out, int total4) {
    int i = blockIdx.x * blockDim.x + threadIdx.x;
    if (i >= total4) return;
    float4 v = ((float4*)out)[i];
    int c = (i & 31) * 4;
    float4 sc = *(const float4*)(g_scale + c);
    float4 sh = *(const float4*)(g_shift + c);
    v.x = fmaxf(fmaf(v.x, sc.x, sh.x), 0.f);
    v.y = fmaxf(fmaf(v.y, sc.y, sh.y), 0.f);
    v.z = fmaxf(fmaf(v.z, sc.z, sh.z), 0.f);
    v.w = fmaxf(fmaf(v.w, sc.w, sh.w), 0.f);
    ((float4*)out)[i] = v;
}

// ---------------------------------------------------------------------------
extern "C" void kernel_launch(void* const* d_in, const int* in_sizes, int n_in,
                              void* d_out, int out_size) {
    const float* x   = (const float*)d_in[0];
    const int*   ei  = (const int*)d_in[1];
    const float* W1l = (const float*)d_in[2];
    const float* b1  = (const float*)d_in[3];
    const float* W1r = (const float*)d_in[4];
    const float* g1  = (const float*)d_in[5];
    const float* be1 = (const float*)d_in[6];
    const float* W2l = (const float*)d_in[7];
    const float* b2  = (const float*)d_in[8];
    const float* W2r = (const float*)d_in[9];
    const float* g2  = (const float*)d_in[10];
    const float* be2 = (const float*)d_in[11];
    float* out = (float*)d_out;

    const int n = in_sizes[0] / 64;
    const int E = in_sizes[1] / 2;

    void *aggp, *h1p, *statp, *degp, *w2pp, *uvp;
    cudaGetSymbolAddress(&aggp, g_agg);
    cudaGetSymbolAddress(&h1p, g_h1);
    cudaGetSymbolAddress(&statp, g_stats);
    cudaGetSymbolAddress(&degp, g_deg);
    cudaGetSymbolAddress(&w2pp, g_w2p);
    cudaGetSymbolAddress(&uvp, g_uv);
    float* agg1   = (float*)aggp;
    float* agg2   = (float*)aggp + (size_t)MAXN * 64;
    float* h1     = (float*)h1p;
    float* stats1 = (float*)statp;
    float* stats2 = (float*)statp + 8192;
    float* deg    = (float*)degp;
    float* W2lp   = (float*)w2pp;
    float* W2rp   = (float*)w2pp + 16384;
    float* uv     = (float*)uvp;

    const int SMEM1 = 2 * 64 * 128 * 4 + 65536;    // 128 KB
    const int SMEM2 = 2 * 128 * 128 * 4 + 65536;   // 192 KB
    cudaFuncSetAttribute(sage_gemm_p<64, false>,
                         cudaFuncAttributeMaxDynamicSharedMemorySize, SMEM1);
    cudaFuncSetAttribute(sage_gemm_p<128, true>,
                         cudaFuncAttributeMaxDynamicSharedMemorySize, SMEM2);

    const int ntiles = (n + 127) / 128;

    // Upfront clears
    cudaMemsetAsync(aggp, 0, ((size_t)MAXN * 64 + (size_t)n * 128) * sizeof(float));
    cudaMemsetAsync(statp, 0, 16384 * sizeof(float));
    cudaMemsetAsync(degp, 0, (size_t)n * sizeof(float));
    cudaMemsetAsync(uvp, 0, 256 * sizeof(float));

    compute_deg<<<(E + 255) / 256, 256>>>(ei, E, deg);

    // ---------------- Layer 1 ----------------
    {
        int total = E * 8;
        sage_scatter<64, 8><<<(total + 255) / 256, 256>>>(x, ei, E, agg1, 0);
        sage_scatter<64, 8><<<(total + 255) / 256, 256>>>(x, ei, E, agg1, 32);
    }
    sage_gemm_p<64, false><<<148, 512, SMEM1>>>(agg1, x, W1l, W1r, b1,
                                                nullptr, nullptr, h1, stats1, n, ntiles);
    bn_finalize<<<1, 128>>>(g1, be1, stats1, 1.0f / (float)n);
    prep_layer2<<<16, 256>>>(W2l, W2r, W2lp, W2rp, uv);

    // ---------------- Layer 2 ----------------
    {
        int total = E * 16;
        sage_scatter<128, 16><<<(total + 255) / 256, 256>>>(h1, ei, E, agg2, 0);
        sage_scatter<128, 16><<<(total + 255) / 256, 256>>>(h1, ei, E, agg2, 64);
    }
    sage_gemm_p<128, true><<<148, 512, SMEM2>>>(agg2, h1, W2lp, W2rp, b2,
                                                uv, deg, out, stats2, n, ntiles);
    bn_finalize<<<1, 128>>>(g2, be2, stats2, 1.0f / (float)n);
    bn_apply_relu<<<((n * 32) + 255) / 256, 256>>>(out, n * 32);
}

// round 8
// speedup vs baseline: 1.8928x; 1.1164x over previous
#include <cuda_runtime.h>
#include <cstdint>

typedef unsigned long long u64;

#define MAXN 200704
#define MAXE 1250048
__device__ float g_agg[(size_t)MAXN * 192];
__device__ float g_h1[(size_t)MAXN * 128];
__device__ int   g_degi[MAXN];
__device__ int   g_rowptr[MAXN + 8];
__device__ int   g_cur[MAXN];
__device__ int   g_csr[MAXE];
__device__ int   g_bsum[1032];
__device__ float g_w2p[32768];     // folded W2l' then W2r'
__device__ float g_uv[256];        // u = t@W2l ; v = t@W2r
__device__ float g_stats[16384];   // layer L at L*8192: [sum 128x32][sq 128x32]
__device__ float g_scale[128];
__device__ float g_shift[128];

// ---------------------------------------------------------------------------
__device__ __forceinline__ void red_add1(float* p, float v) {
    asm volatile("red.global.add.f32 [%0], %1;" :: "l"(p), "f"(v) : "memory");
}
__device__ __forceinline__ void ffma2(u64& d, u64 a, u64 b) {
    asm("fma.rn.f32x2 %0, %1, %2, %0;" : "+l"(d) : "l"(a), "l"(b));
}
__device__ __forceinline__ u64 pack2(float x) {
    u64 r;
    asm("mov.b64 %0, {%1, %1};" : "=l"(r) : "f"(x));
    return r;
}
__device__ __forceinline__ float2 unpack2(u64 v) {
    float2 f;
    asm("mov.b64 {%0, %1}, %2;" : "=f"(f.x), "=f"(f.y) : "l"(v));
    return f;
}
__device__ __forceinline__ void cp16(uint32_t dst, const void* src, bool pred) {
    asm volatile("cp.async.cg.shared.global [%0], [%1], 16, %2;"
                 :: "r"(dst), "l"(src), "r"(pred ? 16 : 0) : "memory");
}
#define CP_COMMIT() asm volatile("cp.async.commit_group;" ::: "memory")
#define CP_WAIT(N)  asm volatile("cp.async.wait_group %0;" :: "n"(N) : "memory")

// ---------------------------------------------------------------------------
// CSR build: histogram -> 3-step exclusive scan -> bucket fill
// ---------------------------------------------------------------------------
__global__ void csr_hist(const int* __restrict__ ei, int E, int* __restrict__ degi) {
    int e = blockIdx.x * blockDim.x + threadIdx.x;
    if (e >= E) return;
    atomicAdd(&degi[ei[E + e]], 1);
}

__global__ void scanA(const int* __restrict__ degi, int n,
                      int* __restrict__ locex, int* __restrict__ bsum) {
    int i = blockIdx.x * 256 + threadIdx.x;
    int v = (i < n) ? degi[i] : 0;
    int lane = threadIdx.x & 31, w = threadIdx.x >> 5;
    int x = v;
#pragma unroll
    for (int o = 1; o < 32; o <<= 1) {
        int t = __shfl_up_sync(0xFFFFFFFFu, x, o);
        if (lane >= o) x += t;
    }
    __shared__ int ws[8], wp[8];
    if (lane == 31) ws[w] = x;
    __syncthreads();
    if (threadIdx.x == 0) {
        int run = 0;
#pragma unroll
        for (int j = 0; j < 8; j++) { wp[j] = run; run += ws[j]; }
        bsum[blockIdx.x] = run;
    }
    __syncthreads();
    if (i < MAXN) locex[i] = x - v + wp[w];
}

__global__ void scanB(int* __restrict__ bsum, int nb) {
    __shared__ int s[1024];
    int t = threadIdx.x;
    int v = (t < nb) ? bsum[t] : 0;
    s[t] = v;
    __syncthreads();
    for (int o = 1; o < 1024; o <<= 1) {
        int add = (t >= o) ? s[t - o] : 0;
        __syncthreads();
        s[t] += add;
        __syncthreads();
    }
    if (t < nb) bsum[t] = s[t] - v;   // exclusive
}

__global__ void scanC(const int* __restrict__ locex, const int* __restrict__ bsum,
                      int n, int E, int* __restrict__ rowptr, int* __restrict__ cur) {
    int i = blockIdx.x * 256 + threadIdx.x;
    if (i < n) {
        int r = locex[i] + bsum[blockIdx.x];
        rowptr[i] = r;
        cur[i] = r;
    }
    if (i == 0) rowptr[n] = E;
}

__global__ void csr_fill(const int* __restrict__ ei, int E,
                         int* __restrict__ cur, int* __restrict__ csr) {
    int e = blockIdx.x * blockDim.x + threadIdx.x;
    if (e >= E) return;
    int s = ei[e], d = ei[E + e];
    int pos = atomicAdd(&cur[d], 1);
    csr[pos] = s;
}

// ---------------------------------------------------------------------------
// Gather aggregation: one warp per dst node, F/8 lanes per edge, half-row pass.
// agg written exactly once (no atomics, no zero-init needed).
// ---------------------------------------------------------------------------
template <int F>
__global__ void sage_gather(const float* __restrict__ feat,
                            const int* __restrict__ rowptr,
                            const int* __restrict__ csr,
                            float* __restrict__ agg, int n, int f_lo) {
    constexpr int LPE = F / 8;       // lanes per edge (half-row/4)
    constexpr int EP  = 32 / LPE;    // edges in parallel
    int gw = (blockIdx.x * blockDim.x + threadIdx.x) >> 5;
    if (gw >= n) return;
    int lane  = threadIdx.x & 31;
    int eslot = lane / LPE;
    int fo    = f_lo + (lane % LPE) * 4;
    int b = rowptr[gw], e = rowptr[gw + 1];
    float4 acc = make_float4(0.f, 0.f, 0.f, 0.f);
    for (int i = b + eslot; i < e; i += EP) {
        int s = csr[i];
        float4 v = *(const float4*)(feat + (size_t)s * F + fo);
        acc.x += v.x; acc.y += v.y; acc.z += v.z; acc.w += v.w;
    }
#pragma unroll
    for (int o = LPE; o < 32; o <<= 1) {
        acc.x += __shfl_down_sync(0xFFFFFFFFu, acc.x, o);
        acc.y += __shfl_down_sync(0xFFFFFFFFu, acc.y, o);
        acc.z += __shfl_down_sync(0xFFFFFFFFu, acc.z, o);
        acc.w += __shfl_down_sync(0xFFFFFFFFu, acc.w, o);
    }
    if (eslot == 0)
        *(float4*)(agg + (size_t)gw * F + fo) = acc;
}

// Fold BN1 into layer-2 weights: W' = diag(s)W ; u = t@W2l ; v = t@W2r
__global__ void prep_layer2(const float* __restrict__ W2l,
                            const float* __restrict__ W2r,
                            float* __restrict__ W2lp, float* __restrict__ W2rp,
                            float* __restrict__ uv) {
    int nidx = threadIdx.x & 127;
    int ko   = threadIdx.x >> 7;
    int kb   = blockIdx.x * 8;
    float usum = 0.f, vsum = 0.f;
#pragma unroll
    for (int i = 0; i < 4; i++) {
        int k = kb + i * 2 + ko;
        float s = g_scale[k], t = g_shift[k];
        float wl = W2l[k * 128 + nidx];
        float wr = W2r[k * 128 + nidx];
        W2lp[k * 128 + nidx] = wl * s;
        W2rp[k * 128 + nidx] = wr * s;
        usum += t * wl;
        vsum += t * wr;
    }
    red_add1(&uv[nidx], usum);
    red_add1(&uv[128 + nidx], vsum);
}

// ---------------------------------------------------------------------------
// Persistent dual GEMM (packed f32x2), 512 threads, 128x128 tile,
// cp.async double-buffered 32-k chunks. add_r = bias | (b2+v)+deg[r]*u.
// ---------------------------------------------------------------------------
template <int K, bool DEG>
__global__ void __launch_bounds__(512, 1)
sage_gemm_p(const float* __restrict__ agg,
            const float* __restrict__ xin,
            const float* __restrict__ Wl,
            const float* __restrict__ Wr,
            const float* __restrict__ bias,
            const float* __restrict__ uv,
            const int* __restrict__ degi,
            float* __restrict__ out, float* __restrict__ stats,
            int n, int ntiles) {
    extern __shared__ float smem[];
    float* sWl = smem;
    float* sWr = smem + K * 128;
    float* chf = smem + 2 * K * 128;       // 2 bufs x (A 4096f + X 4096f)
    const uint32_t chb = (uint32_t)__cvta_generic_to_shared(chf);
    constexpr int NCH = K / 32;

    const int tid  = threadIdx.x;
    const int lane = tid & 15;
    const int rgrp = tid >> 4;
    const int r0   = rgrp * 4;
    const int colA = lane * 4;
    const int colB = 64 + lane * 4;

    for (int i = tid * 4; i < K * 128; i += 2048) {
        *(float4*)(sWl + i) = *(const float4*)(Wl + i);
        *(float4*)(sWr + i) = *(const float4*)(Wr + i);
    }
    __syncthreads();

    float bs[8], us[8];
#pragma unroll
    for (int c = 0; c < 4; c++) {
        int ca = colA + c, cb2 = colB + c;
        if (DEG) {
            bs[c]     = bias[ca]  + uv[128 + ca];
            bs[4 + c] = bias[cb2] + uv[128 + cb2];
            us[c]     = uv[ca];
            us[4 + c] = uv[cb2];
        } else {
            bs[c]     = bias[ca];
            bs[4 + c] = bias[cb2];
        }
    }

    const int seg0 = tid * 2;

    for (int tile = blockIdx.x; tile < ntiles; tile += gridDim.x) {
        const int row0 = tile << 7;

        {
#pragma unroll
            for (int j = 0; j < 2; j++) {
                int seg = seg0 + j, r = seg >> 3, s8 = seg & 7;
                int gr = row0 + r;
                bool p = gr < n;
                const float* sa = agg + (size_t)gr * K + s8 * 4;
                const float* sx = xin + (size_t)gr * K + s8 * 4;
                uint32_t d = chb + (uint32_t)(r * 32 + s8 * 4) * 4;
                cp16(d, sa, p);
                cp16(d + 16384, sx, p);
            }
            CP_COMMIT();
        }

        u64 acc[4][4];
#pragma unroll
        for (int r = 0; r < 4; r++)
#pragma unroll
            for (int p = 0; p < 4; p++) acc[r][p] = 0ull;

        for (int c = 0; c < NCH; c++) {
            const int b = c & 1;
            if (c + 1 < NCH) {
                const int k0n = (c + 1) * 32, bn = (c + 1) & 1;
#pragma unroll
                for (int j = 0; j < 2; j++) {
                    int seg = seg0 + j, r = seg >> 3, s8 = seg & 7;
                    int gr = row0 + r;
                    bool p = gr < n;
                    const float* sa = agg + (size_t)gr * K + k0n + s8 * 4;
                    const float* sx = xin + (size_t)gr * K + k0n + s8 * 4;
                    uint32_t d = chb + (uint32_t)bn * 32768 + (uint32_t)(r * 32 + s8 * 4) * 4;
                    cp16(d, sa, p);
                    cp16(d + 16384, sx, p);
                }
                CP_COMMIT();
                CP_WAIT(1);
            } else {
                CP_WAIT(0);
            }
            __syncthreads();

            const float* sA = chf + b * 8192;
            const float* sX = sA + 4096;
            const int kw0 = c * 32;
#pragma unroll 2
            for (int k = 0; k < 32; k += 4) {
                float4 a4[4], x4[4];
#pragma unroll
                for (int r = 0; r < 4; r++) {
                    a4[r] = *(const float4*)(sA + (r0 + r) * 32 + k);
                    x4[r] = *(const float4*)(sX + (r0 + r) * 32 + k);
                }
#pragma unroll
                for (int kk = 0; kk < 4; kk++) {
                    const int kw = (kw0 + k + kk) * 128;
                    const ulonglong2 wla = *(const ulonglong2*)(sWl + kw + colA);
                    const ulonglong2 wlb = *(const ulonglong2*)(sWl + kw + colB);
                    const ulonglong2 wra = *(const ulonglong2*)(sWr + kw + colA);
                    const ulonglong2 wrb = *(const ulonglong2*)(sWr + kw + colB);
#pragma unroll
                    for (int r = 0; r < 4; r++) {
                        const u64 a2 = pack2((&a4[r].x)[kk]);
                        const u64 b2 = pack2((&x4[r].x)[kk]);
                        ffma2(acc[r][0], a2, wla.x); ffma2(acc[r][0], b2, wra.x);
                        ffma2(acc[r][1], a2, wla.y); ffma2(acc[r][1], b2, wra.y);
                        ffma2(acc[r][2], a2, wlb.x); ffma2(acc[r][2], b2, wrb.x);
                        ffma2(acc[r][3], a2, wlb.y); ffma2(acc[r][3], b2, wrb.y);
                    }
                }
            }
            __syncthreads();
        }

        // ---- epilogue ----
        float* redS = chf;
        float* redQ = chf + 4096;
        float psum[8], psq[8];
#pragma unroll
        for (int c = 0; c < 8; c++) { psum[c] = 0.f; psq[c] = 0.f; }

#pragma unroll
        for (int r = 0; r < 4; r++) {
            int gr = row0 + r0 + r;
            if (gr >= n) continue;
            float dg = DEG ? (float)degi[gr] : 0.f;
            float v[8];
#pragma unroll
            for (int p = 0; p < 4; p++) {
                float2 f = unpack2(acc[r][p]);
                v[p * 2]     = f.x;
                v[p * 2 + 1] = f.y;
            }
#pragma unroll
            for (int c = 0; c < 8; c++) {
                float add = DEG ? (bs[c] + dg * us[c]) : bs[c];
                float tval = fmaxf(v[c] + add, 0.f);
                v[c] = tval;
                psum[c] += tval;
                psq[c]  += tval * tval;
            }
            *(float4*)(out + (size_t)gr * 128 + colA) = make_float4(v[0], v[1], v[2], v[3]);
            *(float4*)(out + (size_t)gr * 128 + colB) = make_float4(v[4], v[5], v[6], v[7]);
        }

#pragma unroll
        for (int c = 0; c < 4; c++) {
            redS[rgrp * 128 + colA + c] = psum[c];
            redS[rgrp * 128 + colB + c] = psum[4 + c];
            redQ[rgrp * 128 + colA + c] = psq[c];
            redQ[rgrp * 128 + colB + c] = psq[4 + c];
        }
        __syncthreads();
        if (tid < 128) {
            float s = 0.f, q = 0.f;
#pragma unroll
            for (int g = 0; g < 32; g++) {
                s += redS[g * 128 + tid];
                q += redQ[g * 128 + tid];
            }
            int slot = tile & 31;
            red_add1(&stats[tid * 32 + slot], s);
            red_add1(&stats[4096 + tid * 32 + slot], q);
        }
        __syncthreads();
    }
}

// ---------------------------------------------------------------------------
__global__ void bn_finalize(const float* __restrict__ gamma,
                            const float* __restrict__ beta,
                            const float* __restrict__ stats, float inv_n) {
    int c = threadIdx.x;
    float s = 0.f, q = 0.f;
#pragma unroll
    for (int j = 0; j < 32; j++) {
        s += stats[c * 32 + j];
        q += stats[4096 + c * 32 + j];
    }
    float mu  = s * inv_n;
    float var = q * inv_n - mu * mu;
    float sc  = gamma[c] * rsqrtf(var + 1e-5f);
    g_scale[c] = sc;
    g_shift[c] = beta[c] - mu * sc;
}

__global__ void bn_apply_relu(float* __restrict__ out, int total4) {
    int i = blockIdx.x * blockDim.x + threadIdx.x;
    if (i >= total4) return;
    float4 v = ((float4*)out)[i];
    int c = (i & 31) * 4;
    float4 sc = *(const float4*)(g_scale + c);
    float4 sh = *(const float4*)(g_shift + c);
    v.x = fmaxf(fmaf(v.x, sc.x, sh.x), 0.f);
    v.y = fmaxf(fmaf(v.y, sc.y, sh.y), 0.f);
    v.z = fmaxf(fmaf(v.z, sc.z, sh.z), 0.f);
    v.w = fmaxf(fmaf(v.w, sc.w, sh.w), 0.f);
    ((float4*)out)[i] = v;
}

// ---------------------------------------------------------------------------
extern "C" void kernel_launch(void* const* d_in, const int* in_sizes, int n_in,
                              void* d_out, int out_size) {
    const float* x   = (const float*)d_in[0];
    const int*   ei  = (const int*)d_in[1];
    const float* W1l = (const float*)d_in[2];
    const float* b1  = (const float*)d_in[3];
    const float* W1r = (const float*)d_in[4];
    const float* g1  = (const float*)d_in[5];
    const float* be1 = (const float*)d_in[6];
    const float* W2l = (const float*)d_in[7];
    const float* b2  = (const float*)d_in[8];
    const float* W2r = (const float*)d_in[9];
    const float* g2  = (const float*)d_in[10];
    const float* be2 = (const float*)d_in[11];
    float* out = (float*)d_out;

    const int n = in_sizes[0] / 64;
    const int E = in_sizes[1] / 2;

    void *aggp, *h1p, *statp, *degp, *rowp, *curp, *csrp, *bsump, *w2pp, *uvp;
    cudaGetSymbolAddress(&aggp, g_agg);
    cudaGetSymbolAddress(&h1p, g_h1);
    cudaGetSymbolAddress(&statp, g_stats);
    cudaGetSymbolAddress(&degp, g_degi);
    cudaGetSymbolAddress(&rowp, g_rowptr);
    cudaGetSymbolAddress(&curp, g_cur);
    cudaGetSymbolAddress(&csrp, g_csr);
    cudaGetSymbolAddress(&bsump, g_bsum);
    cudaGetSymbolAddress(&w2pp, g_w2p);
    cudaGetSymbolAddress(&uvp, g_uv);
    float* agg1   = (float*)aggp;
    float* agg2   = (float*)aggp + (size_t)MAXN * 64;
    float* h1     = (float*)h1p;
    float* stats1 = (float*)statp;
    float* stats2 = (float*)statp + 8192;
    int*   degi   = (int*)degp;
    int*   rowptr = (int*)rowp;
    int*   cur    = (int*)curp;
    int*   csr    = (int*)csrp;
    int*   bsum   = (int*)bsump;
    float* W2lp   = (float*)w2pp;
    float* W2rp   = (float*)w2pp + 16384;
    float* uv     = (float*)uvp;

    const int SMEM1 = 2 * 64 * 128 * 4 + 65536;    // 128 KB
    const int SMEM2 = 2 * 128 * 128 * 4 + 65536;   // 192 KB
    cudaFuncSetAttribute(sage_gemm_p<64, false>,
                         cudaFuncAttributeMaxDynamicSharedMemorySize, SMEM1);
    cudaFuncSetAttribute(sage_gemm_p<128, true>,
                         cudaFuncAttributeMaxDynamicSharedMemorySize, SMEM2);

    const int ntiles = (n + 127) / 128;
    const int nsb = (n + 255) / 256;         // scan blocks (<=784)
    const int gblocks = (n * 32 + 255) / 256; // gather: warp per node

    // small clears only (agg no longer needs zero-init)
    cudaMemsetAsync(degp, 0, (size_t)n * sizeof(int));
    cudaMemsetAsync(statp, 0, 16384 * sizeof(float));
    cudaMemsetAsync(uvp, 0, 256 * sizeof(float));

    // ---------------- CSR build (shared by both layers) ----------------
    csr_hist<<<(E + 255) / 256, 256>>>(ei, E, degi);
    scanA<<<nsb, 256>>>(degi, n, cur /*reuse as locex*/, bsum);
    scanB<<<1, 1024>>>(bsum, nsb);
    scanC<<<nsb, 256>>>(cur, bsum, n, E, rowptr, cur);
    csr_fill<<<(E + 255) / 256, 256>>>(ei, E, cur, csr);

    // ---------------- Layer 1 ----------------
    sage_gather<64><<<gblocks, 256>>>(x, rowptr, csr, agg1, n, 0);
    sage_gather<64><<<gblocks, 256>>>(x, rowptr, csr, agg1, n, 32);
    sage_gemm_p<64, false><<<148, 512, SMEM1>>>(agg1, x, W1l, W1r, b1,
                                                nullptr, nullptr, h1, stats1, n, ntiles);
    bn_finalize<<<1, 128>>>(g1, be1, stats1, 1.0f / (float)n);
    prep_layer2<<<16, 256>>>(W2l, W2r, W2lp, W2rp, uv);

    // ---------------- Layer 2 ----------------
    sage_gather<128><<<gblocks, 256>>>(h1, rowptr, csr, agg2, n, 0);
    sage_gather<128><<<gblocks, 256>>>(h1, rowptr, csr, agg2, n, 64);
    sage_gemm_p<128, true><<<148, 512, SMEM2>>>(agg2, h1, W2lp, W2rp, b2,
                                                uv, degi, out, stats2, n, ntiles);
    bn_finalize<<<1, 128>>>(g2, be2, stats2, 1.0f / (float)n);
    bn_apply_relu<<<((n * 32) + 255) / 256, 256>>>(out, n * 32);
}

// round 10
// speedup vs baseline: 1.9968x; 1.0549x over previous
#include <cuda_runtime.h>
#include <cuda_bf16.h>
#include <cstdint>

#define MAXN 200704
#define MAXE 1250048
__device__ float g_agg[(size_t)MAXN * 192];
__device__ float g_h1[(size_t)MAXN * 128];
__device__ int   g_degi[MAXN];
__device__ int   g_rowptr[MAXN + 8];
__device__ int   g_cur[MAXN];
__device__ int   g_csr[MAXE];
__device__ int   g_bsum[1032];
__device__ float g_w2p[32768];     // folded W2l' then W2r'
__device__ float g_uv[256];        // u = t@W2l ; v = t@W2r
__device__ float g_stats[16384];   // layer L at L*8192: [sum 128x32][sq 128x32]
__device__ float g_scale[128];
__device__ float g_shift[128];

// ---------------------------------------------------------------------------
__device__ __forceinline__ void red_add1(float* p, float v) {
    asm volatile("red.global.add.f32 [%0], %1;" :: "l"(p), "f"(v) : "memory");
}
__device__ __forceinline__ uint32_t cvt_tf32(float x) {
    uint32_t r;
    asm("cvt.rna.tf32.f32 %0, %1;" : "=r"(r) : "f"(x));
    return r;
}
__device__ __forceinline__ void mma_tf32(float* d, const uint32_t* a,
                                         uint32_t b0, uint32_t b1) {
    asm volatile("mma.sync.aligned.m16n8k8.row.col.f32.tf32.tf32.f32 "
                 "{%0,%1,%2,%3},{%4,%5,%6,%7},{%8,%9},{%0,%1,%2,%3};"
                 : "+f"(d[0]), "+f"(d[1]), "+f"(d[2]), "+f"(d[3])
                 : "r"(a[0]), "r"(a[1]), "r"(a[2]), "r"(a[3]),
                   "r"(b0), "r"(b1));
}
__device__ __forceinline__ void cp16(uint32_t dst, const void* src, bool pred) {
    asm volatile("cp.async.cg.shared.global [%0], [%1], 16, %2;"
                 :: "r"(dst), "l"(src), "r"(pred ? 16 : 0) : "memory");
}
#define CP_COMMIT() asm volatile("cp.async.commit_group;" ::: "memory")
#define CP_WAIT(N)  asm volatile("cp.async.wait_group %0;" :: "n"(N) : "memory")

// ---------------------------------------------------------------------------
// CSR build: histogram -> 3-step exclusive scan -> bucket fill
// ---------------------------------------------------------------------------
__global__ void csr_hist(const int* __restrict__ ei, int E, int* __restrict__ degi) {
    int e = blockIdx.x * blockDim.x + threadIdx.x;
    if (e >= E) return;
    atomicAdd(&degi[ei[E + e]], 1);
}
__global__ void scanA(const int* __restrict__ degi, int n,
                      int* __restrict__ locex, int* __restrict__ bsum) {
    int i = blockIdx.x * 256 + threadIdx.x;
    int v = (i < n) ? degi[i] : 0;
    int lane = threadIdx.x & 31, w = threadIdx.x >> 5;
    int x = v;
#pragma unroll
    for (int o = 1; o < 32; o <<= 1) {
        int t = __shfl_up_sync(0xFFFFFFFFu, x, o);
        if (lane >= o) x += t;
    }
    __shared__ int ws[8], wp[8];
    if (lane == 31) ws[w] = x;
    __syncthreads();
    if (threadIdx.x == 0) {
        int run = 0;
#pragma unroll
        for (int j = 0; j < 8; j++) { wp[j] = run; run += ws[j]; }
        bsum[blockIdx.x] = run;
    }
    __syncthreads();
    if (i < MAXN) locex[i] = x - v + wp[w];
}
__global__ void scanB(int* __restrict__ bsum, int nb) {
    __shared__ int s[1024];
    int t = threadIdx.x;
    int v = (t < nb) ? bsum[t] : 0;
    s[t] = v;
    __syncthreads();
    for (int o = 1; o < 1024; o <<= 1) {
        int add = (t >= o) ? s[t - o] : 0;
        __syncthreads();
        s[t] += add;
        __syncthreads();
    }
    if (t < nb) bsum[t] = s[t] - v;
}
__global__ void scanC(const int* __restrict__ locex, const int* __restrict__ bsum,
                      int n, int E, int* __restrict__ rowptr, int* __restrict__ cur) {
    int i = blockIdx.x * 256 + threadIdx.x;
    if (i < n) {
        int r = locex[i] + bsum[blockIdx.x];
        rowptr[i] = r;
        cur[i] = r;
    }
    if (i == 0) rowptr[n] = E;
}
__global__ void csr_fill(const int* __restrict__ ei, int E,
                         int* __restrict__ cur, int* __restrict__ csr) {
    int e = blockIdx.x * blockDim.x + threadIdx.x;
    if (e >= E) return;
    int s = ei[e], d = ei[E + e];
    int pos = atomicAdd(&cur[d], 1);
    csr[pos] = s;
}

// ---------------------------------------------------------------------------
// Gather aggregation: one warp per dst node, feature-half passes.
// ---------------------------------------------------------------------------
template <int F>
__global__ void sage_gather(const float* __restrict__ feat,
                            const int* __restrict__ rowptr,
                            const int* __restrict__ csr,
                            float* __restrict__ agg, int n, int f_lo) {
    constexpr int LPE = F / 8;
    constexpr int EP  = 32 / LPE;
    int gw = (blockIdx.x * blockDim.x + threadIdx.x) >> 5;
    if (gw >= n) return;
    int lane  = threadIdx.x & 31;
    int eslot = lane / LPE;
    int fo    = f_lo + (lane % LPE) * 4;
    int b = rowptr[gw], e = rowptr[gw + 1];
    float4 acc = make_float4(0.f, 0.f, 0.f, 0.f);
    for (int i = b + eslot; i < e; i += EP) {
        int s = csr[i];
        float4 v = *(const float4*)(feat + (size_t)s * F + fo);
        acc.x += v.x; acc.y += v.y; acc.z += v.z; acc.w += v.w;
    }
#pragma unroll
    for (int o = LPE; o < 32; o <<= 1) {
        acc.x += __shfl_down_sync(0xFFFFFFFFu, acc.x, o);
        acc.y += __shfl_down_sync(0xFFFFFFFFu, acc.y, o);
        acc.z += __shfl_down_sync(0xFFFFFFFFu, acc.z, o);
        acc.w += __shfl_down_sync(0xFFFFFFFFu, acc.w, o);
    }
    if (eslot == 0)
        *(float4*)(agg + (size_t)gw * F + fo) = acc;
}

// Fold BN1 into layer-2 weights
__global__ void prep_layer2(const float* __restrict__ W2l,
                            const float* __restrict__ W2r,
                            float* __restrict__ W2lp, float* __restrict__ W2rp,
                            float* __restrict__ uv) {
    int nidx = threadIdx.x & 127;
    int ko   = threadIdx.x >> 7;
    int kb   = blockIdx.x * 8;
    float usum = 0.f, vsum = 0.f;
#pragma unroll
    for (int i = 0; i < 4; i++) {
        int k = kb + i * 2 + ko;
        float s = g_scale[k], t = g_shift[k];
        float wl = W2l[k * 128 + nidx];
        float wr = W2r[k * 128 + nidx];
        W2lp[k * 128 + nidx] = wl * s;
        W2rp[k * 128 + nidx] = wr * s;
        usum += t * wl;
        vsum += t * wr;
    }
    red_add1(&uv[nidx], usum);
    red_add1(&uv[128 + nidx], vsum);
}

// ---------------------------------------------------------------------------
// Persistent tensor-core dual GEMM: mma.sync m16n8k8 tf32 with 3-term split.
// out[r,:] = relu(A1[r]@Wl + A2[r]@Wr + add_r); concat K = 2*Kh.
// Fragments loaded with plain LDS (per PTX fragment tables, no ldmatrix).
// A chunks: raw fp32, [128][36] padded rows (bank = 4g+t, conflict-free),
// cp.async double-buffered. W: packed (bf16hi<<16|bf16lo) [n][K+4].
// ---------------------------------------------------------------------------
template <int K, bool DEG>
__global__ void __launch_bounds__(512, 1)
sage_gemm_tc(const float* __restrict__ A1,
             const float* __restrict__ A2,
             const float* __restrict__ Wl,
             const float* __restrict__ Wr,
             const float* __restrict__ bias,
             const float* __restrict__ uv,
             const int* __restrict__ degi,
             float* __restrict__ out, float* __restrict__ stats,
             int n, int ntiles) {
    extern __shared__ char smx[];
    constexpr int Kh  = K / 2;
    constexpr int NCH = K / 32;
    constexpr int WS  = K + 4;               // W row stride (uint32 units)
    constexpr int AS  = 36;                  // A row stride (f32 units)
    constexpr int ABUF = 128 * AS;           // floats per A buffer
    uint32_t* sW = (uint32_t*)smx;           // [128][WS]
    float*    sA = (float*)(smx + 128 * WS * 4);  // 2 x ABUF
    const uint32_t chb = (uint32_t)__cvta_generic_to_shared(sA);

    const int tid    = threadIdx.x;
    const int lane   = tid & 31;
    const int wid    = tid >> 5;
    const int warp_m = wid & 3;
    const int warp_n = wid >> 2;
    const int g      = lane >> 2;    // groupID 0..7
    const int t      = lane & 3;     // threadID_in_group 0..3

    // ---- pack weights: hi/lo bf16 per element, [n][K] transposed ----
    for (int i = tid; i < 128 * Kh; i += 512) {
        int k = i >> 7, nn = i & 127;
        float wl = Wl[i];                        // Wl[k][nn]
        __nv_bfloat16 h = __float2bfloat16(wl);
        __nv_bfloat16 l = __float2bfloat16(wl - __bfloat162float(h));
        sW[nn * WS + k] = ((uint32_t)__bfloat16_as_ushort(h) << 16)
                        | (uint32_t)__bfloat16_as_ushort(l);
        float wr = Wr[i];
        h = __float2bfloat16(wr);
        l = __float2bfloat16(wr - __bfloat162float(h));
        sW[nn * WS + Kh + k] = ((uint32_t)__bfloat16_as_ushort(h) << 16)
                             | (uint32_t)__bfloat16_as_ushort(l);
    }

    // epilogue constants: thread owns cols 32*warp_n + 8*ni + 2*t + j
    float bs[8], us[8];
#pragma unroll
    for (int ni = 0; ni < 4; ni++) {
#pragma unroll
        for (int j = 0; j < 2; j++) {
            int c = 32 * warp_n + 8 * ni + 2 * t + j;
            if (DEG) { bs[ni * 2 + j] = bias[c] + uv[128 + c]; us[ni * 2 + j] = uv[c]; }
            else     { bs[ni * 2 + j] = bias[c]; us[ni * 2 + j] = 0.f; }
        }
    }
    __syncthreads();

    // staging mapping: thread -> row tid>>2, k-seg (tid&3)*8
    const int srow = tid >> 2;
    const int sseg = (tid & 3) * 8;

    for (int tile = blockIdx.x; tile < ntiles; tile += gridDim.x) {
        const int row0 = tile << 7;

        // ---- prefetch chunk 0 ----
        {
            const float* src = A1;               // chunk 0 k<32<=Kh
            int gr = row0 + srow;
            bool p = gr < n;
            uint32_t d = chb + (uint32_t)(srow * AS + sseg) * 4;
            cp16(d,      src + (size_t)gr * Kh + sseg, p);
            cp16(d + 16, src + (size_t)gr * Kh + sseg + 4, p);
            CP_COMMIT();
        }

        float acc[2][4][4];
#pragma unroll
        for (int mi = 0; mi < 2; mi++)
#pragma unroll
            for (int ni = 0; ni < 4; ni++)
#pragma unroll
                for (int q = 0; q < 4; q++) acc[mi][ni][q] = 0.f;

        for (int c = 0; c < NCH; c++) {
            const int b = c & 1;
            if (c + 1 < NCH) {
                const int kg0 = (c + 1) * 32, bn = (c + 1) & 1;
                const float* src = (kg0 < Kh) ? A1 : A2;
                const int kof = kg0 & (Kh - 1);
                int gr = row0 + srow;
                bool p = gr < n;
                uint32_t d = chb + (uint32_t)bn * (ABUF * 4)
                           + (uint32_t)(srow * AS + sseg) * 4;
                cp16(d,      src + (size_t)gr * Kh + kof + sseg, p);
                cp16(d + 16, src + (size_t)gr * Kh + kof + sseg + 4, p);
                CP_COMMIT();
                CP_WAIT(1);
            } else {
                CP_WAIT(0);
            }
            __syncthreads();

            const float* sAb = sA + b * ABUF;
#pragma unroll
            for (int ks = 0; ks < 4; ks++) {
                const int k0 = ks * 8;
                const int kg = c * 32 + k0;
                // B fragments (hoisted over mi): b0=(k=t,n=g), b1=(k=t+4,n=g)
                uint32_t bh0[4], bh1[4], bl0[4], bl1[4];
#pragma unroll
                for (int ni = 0; ni < 4; ni++) {
                    int nb = 32 * warp_n + 8 * ni + g;
                    uint32_t p0 = sW[nb * WS + kg + t];
                    uint32_t p1 = sW[nb * WS + kg + t + 4];
                    bh0[ni] = p0 & 0xFFFF0000u;  bl0[ni] = p0 << 16;
                    bh1[ni] = p1 & 0xFFFF0000u;  bl1[ni] = p1 << 16;
                }
#pragma unroll
                for (int mi = 0; mi < 2; mi++) {
                    const int rb = (32 * warp_m + 16 * mi + g) * AS + k0 + t;
                    // A frags: a0=(g,t) a1=(g+8,t) a2=(g,t+4) a3=(g+8,t+4)
                    float x0 = sAb[rb];
                    float x1 = sAb[rb + 8 * AS];
                    float x2 = sAb[rb + 4];
                    float x3 = sAb[rb + 8 * AS + 4];
                    uint32_t ah[4], al[4];
                    ah[0] = cvt_tf32(x0); al[0] = cvt_tf32(x0 - __uint_as_float(ah[0]));
                    ah[1] = cvt_tf32(x1); al[1] = cvt_tf32(x1 - __uint_as_float(ah[1]));
                    ah[2] = cvt_tf32(x2); al[2] = cvt_tf32(x2 - __uint_as_float(ah[2]));
                    ah[3] = cvt_tf32(x3); al[3] = cvt_tf32(x3 - __uint_as_float(ah[3]));
#pragma unroll
                    for (int ni = 0; ni < 4; ni++) {
                        mma_tf32(acc[mi][ni], ah, bh0[ni], bh1[ni]);
                        mma_tf32(acc[mi][ni], al, bh0[ni], bh1[ni]);
                        mma_tf32(acc[mi][ni], ah, bl0[ni], bl1[ni]);
                    }
                }
            }
            __syncthreads();
        }

        // ---- epilogue: bias(+deg*u), relu, store, BN stats ----
        float psum[8], psq[8];
#pragma unroll
        for (int q = 0; q < 8; q++) { psum[q] = 0.f; psq[q] = 0.f; }

#pragma unroll
        for (int mi = 0; mi < 2; mi++) {
#pragma unroll
            for (int half = 0; half < 2; half++) {
                int gr = row0 + 32 * warp_m + 16 * mi + g + 8 * half;
                if (gr >= n) continue;
                float dg = DEG ? (float)degi[gr] : 0.f;
#pragma unroll
                for (int ni = 0; ni < 4; ni++) {
                    int c0 = 32 * warp_n + 8 * ni + 2 * t;
                    float v0 = acc[mi][ni][2 * half]     + bs[ni * 2]     + dg * us[ni * 2];
                    float v1 = acc[mi][ni][2 * half + 1] + bs[ni * 2 + 1] + dg * us[ni * 2 + 1];
                    v0 = fmaxf(v0, 0.f);
                    v1 = fmaxf(v1, 0.f);
                    psum[ni * 2]     += v0;  psq[ni * 2]     += v0 * v0;
                    psum[ni * 2 + 1] += v1;  psq[ni * 2 + 1] += v1 * v1;
                    *(float2*)(out + (size_t)gr * 128 + c0) = make_float2(v0, v1);
                }
            }
        }
#pragma unroll
        for (int q = 0; q < 8; q++) {
#pragma unroll
            for (int o = 4; o < 32; o <<= 1) {
                psum[q] += __shfl_down_sync(0xFFFFFFFFu, psum[q], o);
                psq[q]  += __shfl_down_sync(0xFFFFFFFFu, psq[q], o);
            }
        }
        if (g == 0) {  // lanes 0-3 hold column totals
            int slot = ((tile & 7) << 2) | warp_m;
#pragma unroll
            for (int q = 0; q < 8; q++) {
                int col = 32 * warp_n + 8 * (q >> 1) + 2 * t + (q & 1);
                red_add1(&stats[col * 32 + slot], psum[q]);
                red_add1(&stats[4096 + col * 32 + slot], psq[q]);
            }
        }
        __syncthreads();
    }
}

// ---------------------------------------------------------------------------
__global__ void bn_finalize(const float* __restrict__ gamma,
                            const float* __restrict__ beta,
                            const float* __restrict__ stats, float inv_n) {
    int c = threadIdx.x;
    float s = 0.f, q = 0.f;
#pragma unroll
    for (int j = 0; j < 32; j++) {
        s += stats[c * 32 + j];
        q += stats[4096 + c * 32 + j];
    }
    float mu  = s * inv_n;
    float var = q * inv_n - mu * mu;
    float sc  = gamma[c] * rsqrtf(var + 1e-5f);
    g_scale[c] = sc;
    g_shift[c] = beta[c] - mu * sc;
}

__global__ void bn_apply_relu(float* __restrict__ out, int total4) {
    int i = blockIdx.x * blockDim.x + threadIdx.x;
    if (i >= total4) return;
    float4 v = ((float4*)out)[i];
    int c = (i & 31) * 4;
    float4 sc = *(const float4*)(g_scale + c);
    float4 sh = *(const float4*)(g_shift + c);
    v.x = fmaxf(fmaf(v.x, sc.x, sh.x), 0.f);
    v.y = fmaxf(fmaf(v.y, sc.y, sh.y), 0.f);
    v.z = fmaxf(fmaf(v.z, sc.z, sh.z), 0.f);
    v.w = fmaxf(fmaf(v.w, sc.w, sh.w), 0.f);
    ((float4*)out)[i] = v;
}

// ---------------------------------------------------------------------------
extern "C" void kernel_launch(void* const* d_in, const int* in_sizes, int n_in,
                              void* d_out, int out_size) {
    const float* x   = (const float*)d_in[0];
    const int*   ei  = (const int*)d_in[1];
    const float* W1l = (const float*)d_in[2];
    const float* b1  = (const float*)d_in[3];
    const float* W1r = (const float*)d_in[4];
    const float* g1  = (const float*)d_in[5];
    const float* be1 = (const float*)d_in[6];
    const float* W2l = (const float*)d_in[7];
    const float* b2  = (const float*)d_in[8];
    const float* W2r = (const float*)d_in[9];
    const float* g2  = (const float*)d_in[10];
    const float* be2 = (const float*)d_in[11];
    float* out = (float*)d_out;

    const int n = in_sizes[0] / 64;
    const int E = in_sizes[1] / 2;

    void *aggp, *h1p, *statp, *degp, *rowp, *curp, *csrp, *bsump, *w2pp, *uvp;
    cudaGetSymbolAddress(&aggp, g_agg);
    cudaGetSymbolAddress(&h1p, g_h1);
    cudaGetSymbolAddress(&statp, g_stats);
    cudaGetSymbolAddress(&degp, g_degi);
    cudaGetSymbolAddress(&rowp, g_rowptr);
    cudaGetSymbolAddress(&curp, g_cur);
    cudaGetSymbolAddress(&csrp, g_csr);
    cudaGetSymbolAddress(&bsump, g_bsum);
    cudaGetSymbolAddress(&w2pp, g_w2p);
    cudaGetSymbolAddress(&uvp, g_uv);
    float* agg1   = (float*)aggp;
    float* agg2   = (float*)aggp + (size_t)MAXN * 64;
    float* h1     = (float*)h1p;
    float* stats1 = (float*)statp;
    float* stats2 = (float*)statp + 8192;
    int*   degi   = (int*)degp;
    int*   rowptr = (int*)rowp;
    int*   cur    = (int*)curp;
    int*   csr    = (int*)csrp;
    int*   bsum   = (int*)bsump;
    float* W2lp   = (float*)w2pp;
    float* W2rp   = (float*)w2pp + 16384;
    float* uv     = (float*)uvp;

    // SMEM: W (128*(K+4)*4) + 2 A bufs (2*128*36*4 = 36864)
    const int SMEM1 = 128 * 132 * 4 + 36864;   // 104448
    const int SMEM2 = 128 * 260 * 4 + 36864;   // 169984
    cudaFuncSetAttribute(sage_gemm_tc<128, false>,
                         cudaFuncAttributeMaxDynamicSharedMemorySize, SMEM1);
    cudaFuncSetAttribute(sage_gemm_tc<256, true>,
                         cudaFuncAttributeMaxDynamicSharedMemorySize, SMEM2);

    const int ntiles = (n + 127) / 128;
    const int nsb = (n + 255) / 256;
    const int gblocks = (n * 32 + 255) / 256;

    cudaMemsetAsync(degp, 0, (size_t)n * sizeof(int));
    cudaMemsetAsync(statp, 0, 16384 * sizeof(float));
    cudaMemsetAsync(uvp, 0, 256 * sizeof(float));

    // ---------------- CSR build ----------------
    csr_hist<<<(E + 255) / 256, 256>>>(ei, E, degi);
    scanA<<<nsb, 256>>>(degi, n, cur, bsum);
    scanB<<<1, 1024>>>(bsum, nsb);
    scanC<<<nsb, 256>>>(cur, bsum, n, E, rowptr, cur);
    csr_fill<<<(E + 255) / 256, 256>>>(ei, E, cur, csr);

    // ---------------- Layer 1 ----------------
    sage_gather<64><<<gblocks, 256>>>(x, rowptr, csr, agg1, n, 0);
    sage_gather<64><<<gblocks, 256>>>(x, rowptr, csr, agg1, n, 32);
    sage_gemm_tc<128, false><<<148, 512, SMEM1>>>(agg1, x, W1l, W1r, b1,
                                                  uv, degi, h1, stats1, n, ntiles);
    bn_finalize<<<1, 128>>>(g1, be1, stats1, 1.0f / (float)n);
    prep_layer2<<<16, 256>>>(W2l, W2r, W2lp, W2rp, uv);

    // ---------------- Layer 2 ----------------
    sage_gather<128><<<gblocks, 256>>>(h1, rowptr, csr, agg2, n, 0);
    sage_gather<128><<<gblocks, 256>>>(h1, rowptr, csr, agg2, n, 64);
    sage_gemm_tc<256, true><<<148, 512, SMEM2>>>(agg2, h1, W2lp, W2rp, b2,
                                                 uv, degi, out, stats2, n, ntiles);
    bn_finalize<<<1, 128>>>(g2, be2, stats2, 1.0f / (float)n);
    bn_apply_relu<<<((n * 32) + 255) / 256, 256>>>(out, n * 32);
}

// round 11
// speedup vs baseline: 2.5201x; 1.2621x over previous
#include <cuda_runtime.h>
#include <cuda_bf16.h>
#include <cstdint>

#define MAXN 200704
#define MAXE 1250048
__device__ float g_agg[(size_t)MAXN * 192];
__device__ float g_h1[(size_t)MAXN * 128];
__device__ int   g_degi[MAXN];
__device__ int   g_rowptr[MAXN + 8];
__device__ int   g_cur[MAXN];
__device__ int   g_csr[MAXE];
__device__ int   g_bsum[1032];
__device__ float g_w2p[32768];     // folded W2l' then W2r'
__device__ float g_uv[256];        // u = t@W2l ; v = t@W2r
__device__ float g_stats[16384];   // layer L at L*8192: [sum 128x32][sq 128x32]
__device__ float g_scale[128];
__device__ float g_shift[128];

// ---------------------------------------------------------------------------
__device__ __forceinline__ void red_add1(float* p, float v) {
    asm volatile("red.global.add.f32 [%0], %1;" :: "l"(p), "f"(v) : "memory");
}
__device__ __forceinline__ void mma_bf16(float* d, const uint32_t* a,
                                         uint32_t b0, uint32_t b1) {
    asm volatile("mma.sync.aligned.m16n8k16.row.col.f32.bf16.bf16.f32 "
                 "{%0,%1,%2,%3},{%4,%5,%6,%7},{%8,%9},{%0,%1,%2,%3};"
                 : "+f"(d[0]), "+f"(d[1]), "+f"(d[2]), "+f"(d[3])
                 : "r"(a[0]), "r"(a[1]), "r"(a[2]), "r"(a[3]),
                   "r"(b0), "r"(b1));
}
// split (x,y) into packed bf16 hi pair (ret) and lo pair (out param)
__device__ __forceinline__ uint32_t bfsplit2(float x, float y, uint32_t& lo2) {
    __nv_bfloat16 hx = __float2bfloat16(x);
    __nv_bfloat16 hy = __float2bfloat16(y);
    __nv_bfloat16 lx = __float2bfloat16(x - __bfloat162float(hx));
    __nv_bfloat16 ly = __float2bfloat16(y - __bfloat162float(hy));
    lo2 = (uint32_t)__bfloat16_as_ushort(lx) | ((uint32_t)__bfloat16_as_ushort(ly) << 16);
    return (uint32_t)__bfloat16_as_ushort(hx) | ((uint32_t)__bfloat16_as_ushort(hy) << 16);
}

// ---------------------------------------------------------------------------
// CSR build: histogram -> 3-step exclusive scan -> bucket fill
// ---------------------------------------------------------------------------
__global__ void csr_hist(const int* __restrict__ ei, int E, int* __restrict__ degi) {
    int e = blockIdx.x * blockDim.x + threadIdx.x;
    if (e >= E) return;
    atomicAdd(&degi[ei[E + e]], 1);
}
__global__ void scanA(const int* __restrict__ degi, int n,
                      int* __restrict__ locex, int* __restrict__ bsum) {
    int i = blockIdx.x * 256 + threadIdx.x;
    int v = (i < n) ? degi[i] : 0;
    int lane = threadIdx.x & 31, w = threadIdx.x >> 5;
    int x = v;
#pragma unroll
    for (int o = 1; o < 32; o <<= 1) {
        int t = __shfl_up_sync(0xFFFFFFFFu, x, o);
        if (lane >= o) x += t;
    }
    __shared__ int ws[8], wp[8];
    if (lane == 31) ws[w] = x;
    __syncthreads();
    if (threadIdx.x == 0) {
        int run = 0;
#pragma unroll
        for (int j = 0; j < 8; j++) { wp[j] = run; run += ws[j]; }
        bsum[blockIdx.x] = run;
    }
    __syncthreads();
    if (i < MAXN) locex[i] = x - v + wp[w];
}
__global__ void scanB(int* __restrict__ bsum, int nb) {
    __shared__ int s[1024];
    int t = threadIdx.x;
    int v = (t < nb) ? bsum[t] : 0;
    s[t] = v;
    __syncthreads();
    for (int o = 1; o < 1024; o <<= 1) {
        int add = (t >= o) ? s[t - o] : 0;
        __syncthreads();
        s[t] += add;
        __syncthreads();
    }
    if (t < nb) bsum[t] = s[t] - v;
}
__global__ void scanC(const int* __restrict__ locex, const int* __restrict__ bsum,
                      int n, int E, int* __restrict__ rowptr, int* __restrict__ cur) {
    int i = blockIdx.x * 256 + threadIdx.x;
    if (i < n) {
        int r = locex[i] + bsum[blockIdx.x];
        rowptr[i] = r;
        cur[i] = r;
    }
    if (i == 0) rowptr[n] = E;
}
__global__ void csr_fill(const int* __restrict__ ei, int E,
                         int* __restrict__ cur, int* __restrict__ csr) {
    int e = blockIdx.x * blockDim.x + threadIdx.x;
    if (e >= E) return;
    int s = ei[e], d = ei[E + e];
    int pos = atomicAdd(&cur[d], 1);
    csr[pos] = s;
}

// ---------------------------------------------------------------------------
// Gather aggregation: one warp per dst node, feature-half passes.
// ---------------------------------------------------------------------------
template <int F>
__global__ void sage_gather(const float* __restrict__ feat,
                            const int* __restrict__ rowptr,
                            const int* __restrict__ csr,
                            float* __restrict__ agg, int n, int f_lo) {
    constexpr int LPE = F / 8;
    constexpr int EP  = 32 / LPE;
    int gw = (blockIdx.x * blockDim.x + threadIdx.x) >> 5;
    if (gw >= n) return;
    int lane  = threadIdx.x & 31;
    int eslot = lane / LPE;
    int fo    = f_lo + (lane % LPE) * 4;
    int b = rowptr[gw], e = rowptr[gw + 1];
    float4 acc = make_float4(0.f, 0.f, 0.f, 0.f);
    for (int i = b + eslot; i < e; i += EP) {
        int s = csr[i];
        float4 v = *(const float4*)(feat + (size_t)s * F + fo);
        acc.x += v.x; acc.y += v.y; acc.z += v.z; acc.w += v.w;
    }
#pragma unroll
    for (int o = LPE; o < 32; o <<= 1) {
        acc.x += __shfl_down_sync(0xFFFFFFFFu, acc.x, o);
        acc.y += __shfl_down_sync(0xFFFFFFFFu, acc.y, o);
        acc.z += __shfl_down_sync(0xFFFFFFFFu, acc.z, o);
        acc.w += __shfl_down_sync(0xFFFFFFFFu, acc.w, o);
    }
    if (eslot == 0)
        *(float4*)(agg + (size_t)gw * F + fo) = acc;
}

// Fold BN1 into layer-2 weights
__global__ void prep_layer2(const float* __restrict__ W2l,
                            const float* __restrict__ W2r,
                            float* __restrict__ W2lp, float* __restrict__ W2rp,
                            float* __restrict__ uv) {
    int nidx = threadIdx.x & 127;
    int ko   = threadIdx.x >> 7;
    int kb   = blockIdx.x * 8;
    float usum = 0.f, vsum = 0.f;
#pragma unroll
    for (int i = 0; i < 4; i++) {
        int k = kb + i * 2 + ko;
        float s = g_scale[k], t = g_shift[k];
        float wl = W2l[k * 128 + nidx];
        float wr = W2r[k * 128 + nidx];
        W2lp[k * 128 + nidx] = wl * s;
        W2rp[k * 128 + nidx] = wr * s;
        usum += t * wl;
        vsum += t * wr;
    }
    red_add1(&uv[nidx], usum);
    red_add1(&uv[128 + nidx], vsum);
}

// ---------------------------------------------------------------------------
// Persistent tensor-core dual GEMM: mma.sync m16n8k16 bf16, 3-term split.
// out[r,:] = relu(A1[r]@Wl + A2[r]@Wr + add_r); concat K = 2*Kh.
// Fragments via plain LDS (PTX fragment tables; validated pattern from R10).
// A chunks staged as separate bf16-hi / bf16-lo arrays, rows padded to 20
// words (bank = 4g+t permutation). W pre-split hi/lo, rows K/2+4 words.
// Double-buffered via register prefetch (LDG -> split -> STS).
// ---------------------------------------------------------------------------
template <int K, bool DEG>
__global__ void __launch_bounds__(512, 1)
sage_gemm_tc(const float* __restrict__ A1,
             const float* __restrict__ A2,
             const float* __restrict__ Wl,
             const float* __restrict__ Wr,
             const float* __restrict__ bias,
             const float* __restrict__ uv,
             const int* __restrict__ degi,
             float* __restrict__ out, float* __restrict__ stats,
             int n, int ntiles) {
    extern __shared__ char smx[];
    constexpr int Kh  = K / 2;
    constexpr int NCH = K / 32;              // 32-k chunks
    constexpr int WW  = K / 2 + 4;           // W row stride in words (≡4 mod 8)
    constexpr int AW  = 128 * 20;            // words per A array (row stride 20)
    uint32_t* sWhi = (uint32_t*)smx;                  // [128][WW]
    uint32_t* sWlo = sWhi + 128 * WW;
    uint32_t* sA   = sWlo + 128 * WW;                 // buf{0,1} x {hi,lo} x AW

    const int tid    = threadIdx.x;
    const int lane   = tid & 31;
    const int wid    = tid >> 5;
    const int warp_m = wid & 3;
    const int warp_n = wid >> 2;
    const int g      = lane >> 2;    // group 0..7
    const int t      = lane & 3;     // thread-in-group 0..3

    // ---- pack weights: per k-pair, hi/lo bf16x2, transposed [n][k] ----
    for (int i = tid; i < 128 * (Kh / 2); i += 512) {
        int kp = i >> 7, nn = i & 127;         // kp = k-pair index
        float w0 = Wl[(2 * kp) * 128 + nn];
        float w1 = Wl[(2 * kp + 1) * 128 + nn];
        uint32_t lo, hi = bfsplit2(w0, w1, lo);
        sWhi[nn * WW + kp] = hi;
        sWlo[nn * WW + kp] = lo;
        w0 = Wr[(2 * kp) * 128 + nn];
        w1 = Wr[(2 * kp + 1) * 128 + nn];
        hi = bfsplit2(w0, w1, lo);
        sWhi[nn * WW + Kh / 2 + kp] = hi;
        sWlo[nn * WW + Kh / 2 + kp] = lo;
    }

    // epilogue constants: thread owns cols 32*warp_n + 8*ni + 2*t + j
    float bs[8], us[8];
#pragma unroll
    for (int ni = 0; ni < 4; ni++) {
#pragma unroll
        for (int j = 0; j < 2; j++) {
            int c = 32 * warp_n + 8 * ni + 2 * t + j;
            if (DEG) { bs[ni * 2 + j] = bias[c] + uv[128 + c]; us[ni * 2 + j] = uv[c]; }
            else     { bs[ni * 2 + j] = bias[c]; us[ni * 2 + j] = 0.f; }
        }
    }
    __syncthreads();

    // staging mapping: thread -> row tid>>2, k-seg (tid&3)*8 (8 floats = 4 pairs)
    const int srow = tid >> 2;
    const int sseg = (tid & 3) * 8;

    for (int tile = blockIdx.x; tile < ntiles; tile += gridDim.x) {
        const int row0 = tile << 7;

        // ---- stage chunk 0 ----
        {
            int gr = row0 + srow;
            float4 v0 = make_float4(0.f,0.f,0.f,0.f), v1 = v0;
            if (gr < n) {
                v0 = *(const float4*)(A1 + (size_t)gr * Kh + sseg);
                v1 = *(const float4*)(A1 + (size_t)gr * Kh + sseg + 4);
            }
            uint4 H, L;
            H.x = bfsplit2(v0.x, v0.y, L.x);
            H.y = bfsplit2(v0.z, v0.w, L.y);
            H.z = bfsplit2(v1.x, v1.y, L.z);
            H.w = bfsplit2(v1.z, v1.w, L.w);
            *(uint4*)(sA + srow * 20 + sseg / 2) = H;
            *(uint4*)(sA + AW + srow * 20 + sseg / 2) = L;
        }
        __syncthreads();

        float acc[2][4][4];
#pragma unroll
        for (int mi = 0; mi < 2; mi++)
#pragma unroll
            for (int ni = 0; ni < 4; ni++)
#pragma unroll
                for (int q = 0; q < 4; q++) acc[mi][ni][q] = 0.f;

        for (int c = 0; c < NCH; c++) {
            const int b = c & 1;
            float4 p0, p1;
            const bool havnext = (c + 1 < NCH);
            if (havnext) {
                const int kg0 = (c + 1) * 32;
                const float* src = (kg0 < Kh) ? A1 : A2;
                const int kof = kg0 & (Kh - 1);
                int gr = row0 + srow;
                p0 = make_float4(0.f,0.f,0.f,0.f); p1 = p0;
                if (gr < n) {
                    p0 = *(const float4*)(src + (size_t)gr * Kh + kof + sseg);
                    p1 = *(const float4*)(src + (size_t)gr * Kh + kof + sseg + 4);
                }
            }

            // ---- MMA over chunk c: 2 k16-steps ----
            uint32_t* sAb = sA + b * (2 * AW);
#pragma unroll
            for (int ks = 0; ks < 2; ks++) {
                const int kw = c * 16 + ks * 8;   // word offset in W rows
                const int aw = ks * 8;            // word offset in A rows
                // B fragments: b0 = word t, b1 = word t+4 (cols = k window)
                uint32_t bh0[4], bh1[4], bl0[4], bl1[4];
#pragma unroll
                for (int ni = 0; ni < 4; ni++) {
                    int nb = 32 * warp_n + 8 * ni + g;
                    bh0[ni] = sWhi[nb * WW + kw + t];
                    bh1[ni] = sWhi[nb * WW + kw + t + 4];
                    bl0[ni] = sWlo[nb * WW + kw + t];
                    bl1[ni] = sWlo[nb * WW + kw + t + 4];
                }
#pragma unroll
                for (int mi = 0; mi < 2; mi++) {
                    const int rb = (32 * warp_m + 16 * mi + g) * 20 + aw + t;
                    uint32_t ah[4], al[4];
                    ah[0] = sAb[rb];                 al[0] = sAb[AW + rb];
                    ah[1] = sAb[rb + 8 * 20];        al[1] = sAb[AW + rb + 8 * 20];
                    ah[2] = sAb[rb + 4];             al[2] = sAb[AW + rb + 4];
                    ah[3] = sAb[rb + 8 * 20 + 4];    al[3] = sAb[AW + rb + 8 * 20 + 4];
#pragma unroll
                    for (int ni = 0; ni < 4; ni++) {
                        mma_bf16(acc[mi][ni], ah, bh0[ni], bh1[ni]);
                        mma_bf16(acc[mi][ni], al, bh0[ni], bh1[ni]);
                        mma_bf16(acc[mi][ni], ah, bl0[ni], bl1[ni]);
                    }
                }
            }

            if (havnext) {
                const int bn = (c + 1) & 1;
                uint4 H, L;
                H.x = bfsplit2(p0.x, p0.y, L.x);
                H.y = bfsplit2(p0.z, p0.w, L.y);
                H.z = bfsplit2(p1.x, p1.y, L.z);
                H.w = bfsplit2(p1.z, p1.w, L.w);
                *(uint4*)(sA + bn * (2 * AW) + srow * 20 + sseg / 2) = H;
                *(uint4*)(sA + bn * (2 * AW) + AW + srow * 20 + sseg / 2) = L;
            }
            __syncthreads();
        }

        // ---- epilogue: bias(+deg*u), relu, store, BN stats ----
        float psum[8], psq[8];
#pragma unroll
        for (int q = 0; q < 8; q++) { psum[q] = 0.f; psq[q] = 0.f; }

#pragma unroll
        for (int mi = 0; mi < 2; mi++) {
#pragma unroll
            for (int half = 0; half < 2; half++) {
                int gr = row0 + 32 * warp_m + 16 * mi + g + 8 * half;
                if (gr >= n) continue;
                float dg = DEG ? (float)degi[gr] : 0.f;
#pragma unroll
                for (int ni = 0; ni < 4; ni++) {
                    int c0 = 32 * warp_n + 8 * ni + 2 * t;
                    float v0 = acc[mi][ni][2 * half]     + bs[ni * 2]     + dg * us[ni * 2];
                    float v1 = acc[mi][ni][2 * half + 1] + bs[ni * 2 + 1] + dg * us[ni * 2 + 1];
                    v0 = fmaxf(v0, 0.f);
                    v1 = fmaxf(v1, 0.f);
                    psum[ni * 2]     += v0;  psq[ni * 2]     += v0 * v0;
                    psum[ni * 2 + 1] += v1;  psq[ni * 2 + 1] += v1 * v1;
                    *(float2*)(out + (size_t)gr * 128 + c0) = make_float2(v0, v1);
                }
            }
        }
#pragma unroll
        for (int q = 0; q < 8; q++) {
#pragma unroll
            for (int o = 4; o < 32; o <<= 1) {
                psum[q] += __shfl_down_sync(0xFFFFFFFFu, psum[q], o);
                psq[q]  += __shfl_down_sync(0xFFFFFFFFu, psq[q], o);
            }
        }
        if (g == 0) {
            int slot = ((tile & 7) << 2) | warp_m;
#pragma unroll
            for (int q = 0; q < 8; q++) {
                int col = 32 * warp_n + 8 * (q >> 1) + 2 * t + (q & 1);
                red_add1(&stats[col * 32 + slot], psum[q]);
                red_add1(&stats[4096 + col * 32 + slot], psq[q]);
            }
        }
        __syncthreads();
    }
}

// ---------------------------------------------------------------------------
__global__ void bn_finalize(const float* __restrict__ gamma,
                            const float* __restrict__ beta,
                            const float* __restrict__ stats, float inv_n) {
    int c = threadIdx.x;
    float s = 0.f, q = 0.f;
#pragma unroll
    for (int j = 0; j < 32; j++) {
        s += stats[c * 32 + j];
        q += stats[4096 + c * 32 + j];
    }
    float mu  = s * inv_n;
    float var = q * inv_n - mu * mu;
    float sc  = gamma[c] * rsqrtf(var + 1e-5f);
    g_scale[c] = sc;
    g_shift[c] = beta[c] - mu * sc;
}

__global__ void bn_apply_relu(float* __restrict__ out, int total4) {
    int i = blockIdx.x * blockDim.x + threadIdx.x;
    if (i >= total4) return;
    float4 v = ((float4*)out)[i];
    int c = (i & 31) * 4;
    float4 sc = *(const float4*)(g_scale + c);
    float4 sh = *(const float4*)(g_shift + c);
    v.x = fmaxf(fmaf(v.x, sc.x, sh.x), 0.f);
    v.y = fmaxf(fmaf(v.y, sc.y, sh.y), 0.f);
    v.z = fmaxf(fmaf(v.z, sc.z, sh.z), 0.f);
    v.w = fmaxf(fmaf(v.w, sc.w, sh.w), 0.f);
    ((float4*)out)[i] = v;
}

// ---------------------------------------------------------------------------
extern "C" void kernel_launch(void* const* d_in, const int* in_sizes, int n_in,
                              void* d_out, int out_size) {
    const float* x   = (const float*)d_in[0];
    const int*   ei  = (const int*)d_in[1];
    const float* W1l = (const float*)d_in[2];
    const float* b1  = (const float*)d_in[3];
    const float* W1r = (const float*)d_in[4];
    const float* g1  = (const float*)d_in[5];
    const float* be1 = (const float*)d_in[6];
    const float* W2l = (const float*)d_in[7];
    const float* b2  = (const float*)d_in[8];
    const float* W2r = (const float*)d_in[9];
    const float* g2  = (const float*)d_in[10];
    const float* be2 = (const float*)d_in[11];
    float* out = (float*)d_out;

    const int n = in_sizes[0] / 64;
    const int E = in_sizes[1] / 2;

    void *aggp, *h1p, *statp, *degp, *rowp, *curp, *csrp, *bsump, *w2pp, *uvp;
    cudaGetSymbolAddress(&aggp, g_agg);
    cudaGetSymbolAddress(&h1p, g_h1);
    cudaGetSymbolAddress(&statp, g_stats);
    cudaGetSymbolAddress(&degp, g_degi);
    cudaGetSymbolAddress(&rowp, g_rowptr);
    cudaGetSymbolAddress(&curp, g_cur);
    cudaGetSymbolAddress(&csrp, g_csr);
    cudaGetSymbolAddress(&bsump, g_bsum);
    cudaGetSymbolAddress(&w2pp, g_w2p);
    cudaGetSymbolAddress(&uvp, g_uv);
    float* agg1   = (float*)aggp;
    float* agg2   = (float*)aggp + (size_t)MAXN * 64;
    float* h1     = (float*)h1p;
    float* stats1 = (float*)statp;
    float* stats2 = (float*)statp + 8192;
    int*   degi   = (int*)degp;
    int*   rowptr = (int*)rowp;
    int*   cur    = (int*)curp;
    int*   csr    = (int*)csrp;
    int*   bsum   = (int*)bsump;
    float* W2lp   = (float*)w2pp;
    float* W2rp   = (float*)w2pp + 16384;
    float* uv     = (float*)uvp;

    // SMEM: 2*(128*WW*4) + 4*(128*20*4)
    const int SMEM1 = 2 * (128 * 68 * 4)  + 40960;   // 110592
    const int SMEM2 = 2 * (128 * 132 * 4) + 40960;   // 176128
    cudaFuncSetAttribute(sage_gemm_tc<128, false>,
                         cudaFuncAttributeMaxDynamicSharedMemorySize, SMEM1);
    cudaFuncSetAttribute(sage_gemm_tc<256, true>,
                         cudaFuncAttributeMaxDynamicSharedMemorySize, SMEM2);

    const int ntiles = (n + 127) / 128;
    const int nsb = (n + 255) / 256;
    const int gblocks = (n * 32 + 255) / 256;

    cudaMemsetAsync(degp, 0, (size_t)n * sizeof(int));
    cudaMemsetAsync(statp, 0, 16384 * sizeof(float));
    cudaMemsetAsync(uvp, 0, 256 * sizeof(float));

    // ---------------- CSR build ----------------
    csr_hist<<<(E + 255) / 256, 256>>>(ei, E, degi);
    scanA<<<nsb, 256>>>(degi, n, cur, bsum);
    scanB<<<1, 1024>>>(bsum, nsb);
    scanC<<<nsb, 256>>>(cur, bsum, n, E, rowptr, cur);
    csr_fill<<<(E + 255) / 256, 256>>>(ei, E, cur, csr);

    // ---------------- Layer 1 ----------------
    sage_gather<64><<<gblocks, 256>>>(x, rowptr, csr, agg1, n, 0);
    sage_gather<64><<<gblocks, 256>>>(x, rowptr, csr, agg1, n, 32);
    sage_gemm_tc<128, false><<<148, 512, SMEM1>>>(agg1, x, W1l, W1r, b1,
                                                  uv, degi, h1, stats1, n, ntiles);
    bn_finalize<<<1, 128>>>(g1, be1, stats1, 1.0f / (float)n);
    prep_layer2<<<16, 256>>>(W2l, W2r, W2lp, W2rp, uv);

    // ---------------- Layer 2 ----------------
    sage_gather<128><<<gblocks, 256>>>(h1, rowptr, csr, agg2, n, 0);
    sage_gather<128><<<gblocks, 256>>>(h1, rowptr, csr, agg2, n, 64);
    sage_gemm_tc<256, true><<<148, 512, SMEM2>>>(agg2, h1, W2lp, W2rp, b2,
                                                 uv, degi, out, stats2, n, ntiles);
    bn_finalize<<<1, 128>>>(g2, be2, stats2, 1.0f / (float)n);
    bn_apply_relu<<<((n * 32) + 255) / 256, 256>>>(out, n * 32);
}